// round 2
// baseline (speedup 1.0000x reference)
#include <cuda_runtime.h>
#include <cuda_bf16.h>
#include <cstddef>

#define NNODES 50000
#define NEDGES 1600000
#define FIN    128
#define HID    256
#define NCLS   40
#define CPAD   64

// ---------------- scratch (static device memory; no allocations) ----------------
__device__ float g_buf0[(size_t)NNODES * HID];   // GEMM output (hs) ping
__device__ float g_buf1[(size_t)NNODES * HID];   // agg output / next GEMM input pong
__device__ float g_hs4[(size_t)NNODES * CPAD];   // padded layer-4 hs
__device__ float g_is[NNODES];                   // 1/sqrt(deg)
__device__ int   g_cnt[NNODES];
__device__ int   g_fill[NNODES];
__device__ int   g_rowptr[NNODES + 1];
__device__ int   g_srcs[NEDGES];                 // src ids grouped by dst (CSR)
__device__ float g_W4pad[HID * CPAD];            // W4 zero-padded 256x64

// ---------------- graph preprocessing ----------------
__global__ void reset_kernel() {
    int i = blockIdx.x * blockDim.x + threadIdx.x;
    if (i < NNODES) { g_cnt[i] = 0; g_fill[i] = 0; }
}

__global__ void degree_kernel(const int* __restrict__ dst) {
    int e = blockIdx.x * blockDim.x + threadIdx.x;
    if (e < NEDGES) atomicAdd(&g_cnt[dst[e]], 1);
}

__global__ void invsqrt_kernel() {
    int i = blockIdx.x * blockDim.x + threadIdx.x;
    if (i < NNODES) g_is[i] = rsqrtf((float)g_cnt[i] + 1.0f);
}

// single-block exclusive scan over g_cnt -> g_rowptr (50001 entries)
__global__ void scan_kernel() {
    __shared__ int sh[1024];
    __shared__ int carry_s;
    int tid = threadIdx.x;
    if (tid == 0) carry_s = 0;
    __syncthreads();
    for (int base = 0; base < NNODES; base += 1024) {
        int i = base + tid;
        int v = (i < NNODES) ? g_cnt[i] : 0;
        sh[tid] = v;
        __syncthreads();
        for (int off = 1; off < 1024; off <<= 1) {
            int t = (tid >= off) ? sh[tid - off] : 0;
            __syncthreads();
            sh[tid] += t;
            __syncthreads();
        }
        int incl = sh[tid];
        int carry = carry_s;
        if (i < NNODES) g_rowptr[i] = carry + incl - v;
        __syncthreads();
        if (tid == 1023) carry_s = carry + sh[1023];
        __syncthreads();
    }
    if (tid == 0) g_rowptr[NNODES] = carry_s;
}

__global__ void fill_kernel(const int* __restrict__ src, const int* __restrict__ dst) {
    int e = blockIdx.x * blockDim.x + threadIdx.x;
    if (e < NEDGES) {
        int d = dst[e];
        int p = atomicAdd(&g_fill[d], 1);
        g_srcs[g_rowptr[d] + p] = src[e];
    }
}

__global__ void padW4_kernel(const float* __restrict__ W4) {
    int i = blockIdx.x * blockDim.x + threadIdx.x;
    if (i < HID * CPAD) {
        int r = i / CPAD, c = i % CPAD;
        g_W4pad[i] = (c < NCLS) ? W4[r * NCLS + c] : 0.0f;
    }
}

// ---------------- SGEMM: C[m,n] = (A[m,:] @ B[:,n]) * g_is[m] ----------------
// Scale is read from the __device__ symbol g_is inside device code.
#define BM 128
#define BN 64
#define BKT 16

__global__ __launch_bounds__(256) void sgemm_scale(
    const float* __restrict__ A, const float* __restrict__ B,
    float* __restrict__ C,
    int M, int K, int Nc)
{
    __shared__ float As[BKT][BM];
    __shared__ float Bs[BKT][BN];
    int tid = threadIdx.x;
    int tx = tid & 15, ty = tid >> 4;
    int row0 = blockIdx.x * BM;
    int col0 = blockIdx.y * BN;

    float acc[8][4];
#pragma unroll
    for (int i = 0; i < 8; i++)
#pragma unroll
        for (int j = 0; j < 4; j++) acc[i][j] = 0.0f;

    for (int k0 = 0; k0 < K; k0 += BKT) {
#pragma unroll
        for (int i = 0; i < 2; i++) {
            int t2 = tid * 2 + i;
            int m = t2 >> 2, c4 = (t2 & 3) * 4;
            int gr = row0 + m;
            float4 v = make_float4(0.f, 0.f, 0.f, 0.f);
            if (gr < M) v = *(const float4*)(A + (size_t)gr * K + k0 + c4);
            As[c4 + 0][m] = v.x; As[c4 + 1][m] = v.y;
            As[c4 + 2][m] = v.z; As[c4 + 3][m] = v.w;
        }
        {
            int r = tid >> 4, c4 = (tid & 15) * 4;
            float4 v = *(const float4*)(B + (size_t)(k0 + r) * Nc + col0 + c4);
            *(float4*)&Bs[r][c4] = v;
        }
        __syncthreads();
#pragma unroll
        for (int kk = 0; kk < BKT; kk++) {
            float a[8], b[4];
            *(float4*)&a[0] = *(const float4*)&As[kk][ty * 8];
            *(float4*)&a[4] = *(const float4*)&As[kk][ty * 8 + 4];
            *(float4*)&b[0] = *(const float4*)&Bs[kk][tx * 4];
#pragma unroll
            for (int i = 0; i < 8; i++)
#pragma unroll
                for (int j = 0; j < 4; j++) acc[i][j] += a[i] * b[j];
        }
        __syncthreads();
    }
#pragma unroll
    for (int i = 0; i < 8; i++) {
        int gr = row0 + ty * 8 + i;
        if (gr < M) {
            float s = g_is[gr];
            float4 v = make_float4(acc[i][0] * s, acc[i][1] * s, acc[i][2] * s, acc[i][3] * s);
            *(float4*)(C + (size_t)gr * Nc + col0 + tx * 4) = v;
        }
    }
}

// ---------------- aggregation (HID=256) ----------------
__global__ __launch_bounds__(256) void agg_relu_kernel(
    const float* __restrict__ hs, const float* __restrict__ bias,
    float* __restrict__ out)
{
    int n = blockIdx.x;
    int f = threadIdx.x;
    int beg = g_rowptr[n], end = g_rowptr[n + 1];
    float a0 = hs[(size_t)n * HID + f];
    float a1 = 0.f, a2 = 0.f, a3 = 0.f;
    int e = beg;
    for (; e + 4 <= end; e += 4) {
        int s0 = g_srcs[e], s1 = g_srcs[e + 1], s2 = g_srcs[e + 2], s3 = g_srcs[e + 3];
        a0 += hs[(size_t)s0 * HID + f];
        a1 += hs[(size_t)s1 * HID + f];
        a2 += hs[(size_t)s2 * HID + f];
        a3 += hs[(size_t)s3 * HID + f];
    }
    for (; e < end; e++) a0 += hs[(size_t)g_srcs[e] * HID + f];
    float acc = (a0 + a1) + (a2 + a3);
    float v = g_is[n] * acc + bias[f];
    out[(size_t)n * HID + f] = fmaxf(v, 0.0f);
}

// ---------------- layer 4: aggregation + bias + log_softmax ----------------
__global__ __launch_bounds__(256) void agg40_lsm_kernel(
    const float* __restrict__ hs4, const float* __restrict__ b4,
    float* __restrict__ out)
{
    int warp = (blockIdx.x * blockDim.x + threadIdx.x) >> 5;
    int lane = threadIdx.x & 31;
    if (warp >= NNODES) return;
    int n = warp;
    int beg = g_rowptr[n], end = g_rowptr[n + 1];
    float a0 = hs4[(size_t)n * CPAD + lane];
    float a1 = hs4[(size_t)n * CPAD + 32 + lane];
    for (int e = beg; e < end; e++) {
        int s = g_srcs[e];
        a0 += hs4[(size_t)s * CPAD + lane];
        a1 += hs4[(size_t)s * CPAD + 32 + lane];
    }
    float sc = g_is[n];
    int f1 = 32 + lane;
    float o0 = sc * a0 + b4[lane];
    float o1 = (f1 < NCLS) ? (sc * a1 + b4[f1]) : -1e30f;
    float m = fmaxf(o0, o1);
#pragma unroll
    for (int off = 16; off; off >>= 1) m = fmaxf(m, __shfl_xor_sync(0xffffffffu, m, off));
    float se = __expf(o0 - m) + ((f1 < NCLS) ? __expf(o1 - m) : 0.0f);
#pragma unroll
    for (int off = 16; off; off >>= 1) se += __shfl_xor_sync(0xffffffffu, se, off);
    float lse = m + __logf(se);
    out[(size_t)n * NCLS + lane] = o0 - lse;
    if (f1 < NCLS) out[(size_t)n * NCLS + f1] = o1 - lse;
}

// ---------------- launch ----------------
extern "C" void kernel_launch(void* const* d_in, const int* in_sizes, int n_in,
                              void* d_out, int out_size)
{
    const float* x  = (const float*)d_in[0];
    const int*   ei = (const int*)  d_in[1];
    const float* W1 = (const float*)d_in[2];
    const float* b1 = (const float*)d_in[3];
    const float* W2 = (const float*)d_in[4];
    const float* b2 = (const float*)d_in[5];
    const float* W3 = (const float*)d_in[6];
    const float* b3 = (const float*)d_in[7];
    const float* W4 = (const float*)d_in[8];
    const float* b4 = (const float*)d_in[9];
    float* out = (float*)d_out;

    const int* src = ei;
    const int* dst = ei + NEDGES;

    float* buf0; float* buf1; float* hs4; float* W4pad;
    cudaGetSymbolAddress((void**)&buf0,  g_buf0);
    cudaGetSymbolAddress((void**)&buf1,  g_buf1);
    cudaGetSymbolAddress((void**)&hs4,   g_hs4);
    cudaGetSymbolAddress((void**)&W4pad, g_W4pad);

    const int TB = 256;
    int nodeBlocks = (NNODES + TB - 1) / TB;
    int edgeBlocks = (NEDGES + TB - 1) / TB;

    reset_kernel<<<nodeBlocks, TB>>>();
    degree_kernel<<<edgeBlocks, TB>>>(dst);
    invsqrt_kernel<<<nodeBlocks, TB>>>();
    scan_kernel<<<1, 1024>>>();
    fill_kernel<<<edgeBlocks, TB>>>(src, dst);
    padW4_kernel<<<(HID * CPAD + TB - 1) / TB, TB>>>(W4);

    dim3 g256((NNODES + BM - 1) / BM, HID / BN);   // 391 x 4
    dim3 g64((NNODES + BM - 1) / BM, CPAD / BN);   // 391 x 1
    int lsmBlocks = (NNODES * 32 + TB - 1) / TB;

    sgemm_scale<<<g256, TB>>>(x, W1, buf0, NNODES, FIN, HID);
    agg_relu_kernel<<<NNODES, TB>>>(buf0, b1, buf1);
    sgemm_scale<<<g256, TB>>>(buf1, W2, buf0, NNODES, HID, HID);
    agg_relu_kernel<<<NNODES, TB>>>(buf0, b2, buf1);
    sgemm_scale<<<g256, TB>>>(buf1, W3, buf0, NNODES, HID, HID);
    agg_relu_kernel<<<NNODES, TB>>>(buf0, b3, buf1);
    sgemm_scale<<<g64, TB>>>(buf1, W4pad, hs4, NNODES, HID, CPAD);
    agg40_lsm_kernel<<<lsmBlocks, TB>>>(hs4, b4, out);
}

// round 5
// speedup vs baseline: 1.3399x; 1.3399x over previous
#include <cuda_runtime.h>
#include <cuda_bf16.h>
#include <cstdint>
#include <cstddef>

#define NNODES 50000
#define NEDGES 1600000
#define FIN    128
#define HID    256
#define NCLS   40
#define CPAD   64
#define NB_SCAN 49   // ceil(50000/1024)

// ================= static device scratch =================
__device__ float g_is[NNODES];
__device__ int   g_cnt[NNODES];
__device__ int   g_fill[NNODES];
__device__ int   g_rowptr[NNODES + 1];
__device__ int   g_srcs[NEDGES];
__device__ int   g_bsum[NB_SCAN];
__device__ int   g_boff[NB_SCAN];

__device__ __nv_bfloat16 g_thi[(size_t)NNODES * FIN];
__device__ __nv_bfloat16 g_tlo[(size_t)NNODES * FIN];
__device__ __nv_bfloat16 g_h0hi[(size_t)NNODES * HID];
__device__ __nv_bfloat16 g_h0lo[(size_t)NNODES * HID];
__device__ __nv_bfloat16 g_h1hi[(size_t)NNODES * HID];
__device__ __nv_bfloat16 g_h1lo[(size_t)NNODES * HID];
__device__ float g_hs[(size_t)NNODES * HID];
__device__ float g_hs4[(size_t)NNODES * CPAD];

// weights transposed+split: Wt[n][k] row-major [Npad][K]
__device__ __nv_bfloat16 g_wt1hi[HID * FIN],  g_wt1lo[HID * FIN];
__device__ __nv_bfloat16 g_wt2hi[HID * HID],  g_wt2lo[HID * HID];
__device__ __nv_bfloat16 g_wt3hi[HID * HID],  g_wt3lo[HID * HID];
__device__ __nv_bfloat16 g_wt4hi[CPAD * HID], g_wt4lo[CPAD * HID];

// ================= PTX helpers (base compute_103-legal only!) =================
__device__ __forceinline__ uint32_t smem_u32(const void* p) {
    uint32_t a;
    asm("{ .reg .u64 t; cvta.to.shared.u64 t, %1; cvt.u32.u64 %0, t; }" : "=r"(a) : "l"(p));
    return a;
}
__device__ __forceinline__ void ldsm_x4(uint32_t& r0, uint32_t& r1, uint32_t& r2, uint32_t& r3,
                                        uint32_t addr) {
    asm volatile("ldmatrix.sync.aligned.m8n8.x4.shared.b16 {%0,%1,%2,%3}, [%4];"
                 : "=r"(r0), "=r"(r1), "=r"(r2), "=r"(r3) : "r"(addr));
}
__device__ __forceinline__ void mma16816(float& c0, float& c1, float& c2, float& c3,
                                         uint32_t a0, uint32_t a1, uint32_t a2, uint32_t a3,
                                         uint32_t b0, uint32_t b1) {
    asm volatile("mma.sync.aligned.m16n8k16.row.col.f32.bf16.bf16.f32 "
                 "{%0,%1,%2,%3}, {%4,%5,%6,%7}, {%8,%9}, {%0,%1,%2,%3};"
                 : "+f"(c0), "+f"(c1), "+f"(c2), "+f"(c3)
                 : "r"(a0), "r"(a1), "r"(a2), "r"(a3), "r"(b0), "r"(b1));
}

// ================= graph preprocessing =================
__global__ void reset_kernel() {
    int i = blockIdx.x * blockDim.x + threadIdx.x;
    if (i < NNODES) { g_cnt[i] = 0; g_fill[i] = 0; }
}
__global__ void degree_kernel(const int* __restrict__ dst) {
    int e = blockIdx.x * blockDim.x + threadIdx.x;
    if (e < NEDGES) atomicAdd(&g_cnt[dst[e]], 1);
}
__global__ void invsqrt_kernel() {
    int i = blockIdx.x * blockDim.x + threadIdx.x;
    if (i < NNODES) g_is[i] = rsqrtf((float)g_cnt[i] + 1.0f);
}
__global__ __launch_bounds__(1024) void scan_block_kernel() {
    __shared__ int ws[32];
    int t = threadIdx.x, b = blockIdx.x;
    int i = b * 1024 + t;
    int v = (i < NNODES) ? g_cnt[i] : 0;
    int lane = t & 31, w = t >> 5;
    int x = v;
#pragma unroll
    for (int off = 1; off < 32; off <<= 1) {
        int y = __shfl_up_sync(0xffffffffu, x, off);
        if (lane >= off) x += y;
    }
    if (lane == 31) ws[w] = x;
    __syncthreads();
    if (w == 0) {
        int s = ws[lane];
#pragma unroll
        for (int off = 1; off < 32; off <<= 1) {
            int y = __shfl_up_sync(0xffffffffu, s, off);
            if (lane >= off) s += y;
        }
        ws[lane] = s;
    }
    __syncthreads();
    int incl = x + (w ? ws[w - 1] : 0);
    if (i < NNODES) g_rowptr[i] = incl - v;
    if (t == 1023) g_bsum[b] = incl;
}
__global__ void scan_tops_kernel() {
    __shared__ int s[64];
    int t = threadIdx.x;
    int v = (t < NB_SCAN) ? g_bsum[t] : 0;
    s[t] = v;
    __syncthreads();
    for (int off = 1; off < 64; off <<= 1) {
        int y = (t >= off) ? s[t - off] : 0;
        __syncthreads();
        s[t] += y;
        __syncthreads();
    }
    if (t < NB_SCAN) g_boff[t] = s[t] - v;
    if (t == NB_SCAN - 1) g_rowptr[NNODES] = s[t];
}
__global__ __launch_bounds__(1024) void scan_add_kernel() {
    int i = blockIdx.x * 1024 + threadIdx.x;
    if (i < NNODES) g_rowptr[i] += g_boff[blockIdx.x];
}
__global__ void fill_kernel(const int* __restrict__ src, const int* __restrict__ dst) {
    int e = blockIdx.x * blockDim.x + threadIdx.x;
    if (e < NEDGES) {
        int d = dst[e];
        int p = atomicAdd(&g_fill[d], 1);
        g_srcs[g_rowptr[d] + p] = src[e];
    }
}
__global__ void wprep_kernel(const float* __restrict__ W, int K, int Nw, int Npad,
                             __nv_bfloat16* __restrict__ dhi, __nv_bfloat16* __restrict__ dlo) {
    int i = blockIdx.x * blockDim.x + threadIdx.x;
    if (i < K * Npad) {
        int n = i / K, k = i % K;
        float v = (n < Nw) ? W[k * Nw + n] : 0.0f;
        __nv_bfloat16 h = __float2bfloat16(v);
        dhi[i] = h;
        dlo[i] = __float2bfloat16(v - __bfloat162float(h));
    }
}

// ================= aggregation kernels =================
__global__ __launch_bounds__(FIN) void agg_x_kernel(const float* __restrict__ x) {
    int n = blockIdx.x;
    int f = threadIdx.x;
    int beg = g_rowptr[n], end = g_rowptr[n + 1];
    float isn = g_is[n];
    float a0 = isn * x[(size_t)n * FIN + f];
    float a1 = 0.f, a2 = 0.f, a3 = 0.f;
    int e = beg;
    for (; e + 4 <= end; e += 4) {
        int s0 = g_srcs[e], s1 = g_srcs[e + 1], s2 = g_srcs[e + 2], s3 = g_srcs[e + 3];
        a0 += g_is[s0] * x[(size_t)s0 * FIN + f];
        a1 += g_is[s1] * x[(size_t)s1 * FIN + f];
        a2 += g_is[s2] * x[(size_t)s2 * FIN + f];
        a3 += g_is[s3] * x[(size_t)s3 * FIN + f];
    }
    for (; e < end; e++) { int s = g_srcs[e]; a0 += g_is[s] * x[(size_t)s * FIN + f]; }
    float v = isn * ((a0 + a1) + (a2 + a3));
    __nv_bfloat16 h = __float2bfloat16(v);
    g_thi[(size_t)n * FIN + f] = h;
    g_tlo[(size_t)n * FIN + f] = __float2bfloat16(v - __bfloat162float(h));
}
__global__ __launch_bounds__(HID) void agg_mid_kernel(
    const float* __restrict__ hs, const float* __restrict__ bias,
    __nv_bfloat16* __restrict__ ohi, __nv_bfloat16* __restrict__ olo) {
    int n = blockIdx.x;
    int f = threadIdx.x;
    int beg = g_rowptr[n], end = g_rowptr[n + 1];
    float a0 = hs[(size_t)n * HID + f];
    float a1 = 0.f, a2 = 0.f, a3 = 0.f;
    int e = beg;
    for (; e + 4 <= end; e += 4) {
        int s0 = g_srcs[e], s1 = g_srcs[e + 1], s2 = g_srcs[e + 2], s3 = g_srcs[e + 3];
        a0 += hs[(size_t)s0 * HID + f];
        a1 += hs[(size_t)s1 * HID + f];
        a2 += hs[(size_t)s2 * HID + f];
        a3 += hs[(size_t)s3 * HID + f];
    }
    for (; e < end; e++) a0 += hs[(size_t)g_srcs[e] * HID + f];
    float v = g_is[n] * ((a0 + a1) + (a2 + a3)) + bias[f];
    v = fmaxf(v, 0.0f);
    __nv_bfloat16 h = __float2bfloat16(v);
    ohi[(size_t)n * HID + f] = h;
    olo[(size_t)n * HID + f] = __float2bfloat16(v - __bfloat162float(h));
}
__global__ __launch_bounds__(256) void agg40_lsm_kernel(
    const float* __restrict__ hs4, const float* __restrict__ b4, float* __restrict__ out) {
    int warp = (blockIdx.x * blockDim.x + threadIdx.x) >> 5;
    int lane = threadIdx.x & 31;
    if (warp >= NNODES) return;
    int n = warp;
    int beg = g_rowptr[n], end = g_rowptr[n + 1];
    float a0 = hs4[(size_t)n * CPAD + lane];
    float a1 = hs4[(size_t)n * CPAD + 32 + lane];
    for (int e = beg; e < end; e++) {
        int s = g_srcs[e];
        a0 += hs4[(size_t)s * CPAD + lane];
        a1 += hs4[(size_t)s * CPAD + 32 + lane];
    }
    float sc = g_is[n];
    int f1 = 32 + lane;
    float o0 = sc * a0 + b4[lane];
    float o1 = (f1 < NCLS) ? (sc * a1 + b4[f1]) : -1e30f;
    float m = fmaxf(o0, o1);
#pragma unroll
    for (int off = 16; off; off >>= 1) m = fmaxf(m, __shfl_xor_sync(0xffffffffu, m, off));
    float se = __expf(o0 - m) + ((f1 < NCLS) ? __expf(o1 - m) : 0.0f);
#pragma unroll
    for (int off = 16; off; off >>= 1) se += __shfl_xor_sync(0xffffffffu, se, off);
    float lse = m + __logf(se);
    out[(size_t)n * NCLS + lane] = o0 - lse;
    if (f1 < NCLS) out[(size_t)n * NCLS + f1] = o1 - lse;
}

// ================= HMMA bf16x2-split GEMM =================
// C[M, NT] = (Ahi+Alo)[m,:K] @ (Bhi+Blo)[n,:K]^T  (lo*lo dropped), fp32 accum.
// MODE 0: Cf[m,n] = D * g_is[m]        (fp32 out)
// MODE 1: relu(D + bias[n]) -> Chi/Clo (bf16 hi/lo out)
// Block: 256 thr = 8 warps as 4(M) x 2(N). CTA tile: 128 x BN_T. K-chunk 64.
#define KC 64
#define SSTR 72   // smem row stride in bf16 (64 data + 8 pad)

template <int BN_T, int MODE>
__global__ __launch_bounds__(256) void mma_gemm_kernel(
    const __nv_bfloat16* __restrict__ Ahi, const __nv_bfloat16* __restrict__ Alo,
    const __nv_bfloat16* __restrict__ Bhi, const __nv_bfloat16* __restrict__ Blo,
    int K, int NT,
    float* __restrict__ Cf,
    __nv_bfloat16* __restrict__ Chi, __nv_bfloat16* __restrict__ Clo,
    const float* __restrict__ bias)
{
    extern __shared__ __nv_bfloat16 sm[];
    constexpr int A_ELEMS = 128 * SSTR;
    constexpr int B_ELEMS = BN_T * SSTR;
    __nv_bfloat16* sAhi = sm;
    __nv_bfloat16* sAlo = sm + A_ELEMS;
    __nv_bfloat16* sBhi = sm + 2 * A_ELEMS;
    __nv_bfloat16* sBlo = sm + 2 * A_ELEMS + B_ELEMS;

    const int tid = threadIdx.x;
    const int lane = tid & 31;
    const int wid = tid >> 5;
    const int wm = wid & 3;          // warp row (0..3) -> M offset wm*32
    const int wn = wid >> 2;         // warp col (0..1) -> N offset wn*(BN_T/2)
    constexpr int WN = BN_T / 2;     // warp N extent
    constexpr int NTILES = WN / 8;   // n-tiles per warp (8 for 128, 4 for 64)

    const int row0 = blockIdx.x * 128;
    const int col0 = blockIdx.y * BN_T;

    float acc[2][NTILES][4];
#pragma unroll
    for (int i = 0; i < 2; i++)
#pragma unroll
        for (int j = 0; j < NTILES; j++)
#pragma unroll
            for (int q = 0; q < 4; q++) acc[i][j][q] = 0.0f;

    // ldmatrix lane-address offsets
    const int a_r = (lane & 7) + ((lane >> 3) & 1) * 8;   // row within 16
    const int a_k = (lane >> 4) * 8;                      // k half
    const int b_n = (lane & 7) + ((lane >> 4) & 1) * 8;   // n within 16
    const int b_k = ((lane >> 3) & 1) * 8;                // k half

    const uint32_t uAhi = smem_u32(sAhi), uAlo = smem_u32(sAlo);
    const uint32_t uBhi = smem_u32(sBhi), uBlo = smem_u32(sBlo);

    for (int k0 = 0; k0 < K; k0 += KC) {
        // ---- load A tiles: 128 rows x 64 bf16 (hi & lo), 16B per thread-iter ----
#pragma unroll
        for (int it = 0; it < 4; it++) {
            int idx = tid + it * 256;          // 0..1023
            int r = idx >> 3, q = idx & 7;
            int gr = row0 + r;
            uint4 vh = make_uint4(0, 0, 0, 0), vl = make_uint4(0, 0, 0, 0);
            if (gr < NNODES) {
                vh = *(const uint4*)(Ahi + (size_t)gr * K + k0 + q * 8);
                vl = *(const uint4*)(Alo + (size_t)gr * K + k0 + q * 8);
            }
            *(uint4*)(sAhi + r * SSTR + q * 8) = vh;
            *(uint4*)(sAlo + r * SSTR + q * 8) = vl;
        }
        // ---- load B tiles: BN_T rows x 64 bf16 ----
#pragma unroll
        for (int it = 0; it < (BN_T * 8 + 255) / 256; it++) {
            int idx = tid + it * 256;
            if (idx < BN_T * 8) {
                int n = idx >> 3, q = idx & 7;
                uint4 vh = *(const uint4*)(Bhi + (size_t)(col0 + n) * K + k0 + q * 8);
                uint4 vl = *(const uint4*)(Blo + (size_t)(col0 + n) * K + k0 + q * 8);
                *(uint4*)(sBhi + n * SSTR + q * 8) = vh;
                *(uint4*)(sBlo + n * SSTR + q * 8) = vl;
            }
        }
        __syncthreads();

#pragma unroll
        for (int ks = 0; ks < KC / 16; ks++) {
            // A fragments (2 m-tiles, hi & lo)
            uint32_t ah[2][4], al[2][4];
#pragma unroll
            for (int mt = 0; mt < 2; mt++) {
                uint32_t off = (uint32_t)(((wm * 32 + mt * 16 + a_r) * SSTR + ks * 16 + a_k) * 2);
                ldsm_x4(ah[mt][0], ah[mt][1], ah[mt][2], ah[mt][3], uAhi + off);
                ldsm_x4(al[mt][0], al[mt][1], al[mt][2], al[mt][3], uAlo + off);
            }
            // B fragments (NTILES n-tiles, hi & lo); one x4 covers 2 n-tiles
            uint32_t bh[NTILES][2], bl[NTILES][2];
#pragma unroll
            for (int nb = 0; nb < NTILES / 2; nb++) {
                uint32_t off = (uint32_t)(((wn * WN + nb * 16 + b_n) * SSTR + ks * 16 + b_k) * 2);
                uint32_t r0, r1, r2, r3;
                ldsm_x4(r0, r1, r2, r3, uBhi + off);
                bh[nb * 2][0] = r0; bh[nb * 2][1] = r1;
                bh[nb * 2 + 1][0] = r2; bh[nb * 2 + 1][1] = r3;
                ldsm_x4(r0, r1, r2, r3, uBlo + off);
                bl[nb * 2][0] = r0; bl[nb * 2][1] = r1;
                bl[nb * 2 + 1][0] = r2; bl[nb * 2 + 1][1] = r3;
            }
#pragma unroll
            for (int mt = 0; mt < 2; mt++)
#pragma unroll
                for (int nt = 0; nt < NTILES; nt++) {
                    mma16816(acc[mt][nt][0], acc[mt][nt][1], acc[mt][nt][2], acc[mt][nt][3],
                             ah[mt][0], ah[mt][1], ah[mt][2], ah[mt][3], bh[nt][0], bh[nt][1]);
                    mma16816(acc[mt][nt][0], acc[mt][nt][1], acc[mt][nt][2], acc[mt][nt][3],
                             ah[mt][0], ah[mt][1], ah[mt][2], ah[mt][3], bl[nt][0], bl[nt][1]);
                    mma16816(acc[mt][nt][0], acc[mt][nt][1], acc[mt][nt][2], acc[mt][nt][3],
                             al[mt][0], al[mt][1], al[mt][2], al[mt][3], bh[nt][0], bh[nt][1]);
                }
        }
        __syncthreads();
    }

    // ---- epilogue ----
    const int rbase = row0 + wm * 32 + (lane >> 2);
    const int cbase = col0 + wn * WN + ((lane & 3) * 2);
#pragma unroll
    for (int mt = 0; mt < 2; mt++) {
#pragma unroll
        for (int half = 0; half < 2; half++) {
            int gr = rbase + mt * 16 + half * 8;
            if (gr < NNODES) {
                if (MODE == 0) {
                    float s = g_is[gr];
#pragma unroll
                    for (int nt = 0; nt < NTILES; nt++) {
                        float2 v;
                        v.x = acc[mt][nt][half * 2 + 0] * s;
                        v.y = acc[mt][nt][half * 2 + 1] * s;
                        *(float2*)(Cf + (size_t)gr * NT + cbase + nt * 8) = v;
                    }
                } else {
#pragma unroll
                    for (int nt = 0; nt < NTILES; nt++) {
                        int c = cbase + nt * 8;
                        float v0 = fmaxf(acc[mt][nt][half * 2 + 0] + bias[c], 0.0f);
                        float v1 = fmaxf(acc[mt][nt][half * 2 + 1] + bias[c + 1], 0.0f);
                        __nv_bfloat16 h0 = __float2bfloat16(v0);
                        __nv_bfloat16 h1 = __float2bfloat16(v1);
                        __nv_bfloat162 hp; hp.x = h0; hp.y = h1;
                        __nv_bfloat162 lp;
                        lp.x = __float2bfloat16(v0 - __bfloat162float(h0));
                        lp.y = __float2bfloat16(v1 - __bfloat162float(h1));
                        *(__nv_bfloat162*)(Chi + (size_t)gr * NT + c) = hp;
                        *(__nv_bfloat162*)(Clo + (size_t)gr * NT + c) = lp;
                    }
                }
            }
        }
    }
}

// ================= launch =================
extern "C" void kernel_launch(void* const* d_in, const int* in_sizes, int n_in,
                              void* d_out, int out_size)
{
    const float* x  = (const float*)d_in[0];
    const int*   ei = (const int*)  d_in[1];
    const float* W1 = (const float*)d_in[2];
    const float* b1 = (const float*)d_in[3];
    const float* W2 = (const float*)d_in[4];
    const float* b2 = (const float*)d_in[5];
    const float* W3 = (const float*)d_in[6];
    const float* b3 = (const float*)d_in[7];
    const float* W4 = (const float*)d_in[8];
    const float* b4 = (const float*)d_in[9];
    float* out = (float*)d_out;

    const int* src = ei;
    const int* dst = ei + NEDGES;

    __nv_bfloat16 *thi, *tlo, *h0hi, *h0lo, *h1hi, *h1lo;
    __nv_bfloat16 *wt1hi, *wt1lo, *wt2hi, *wt2lo, *wt3hi, *wt3lo, *wt4hi, *wt4lo;
    float *hs, *hs4;
    cudaGetSymbolAddress((void**)&thi,  g_thi);   cudaGetSymbolAddress((void**)&tlo,  g_tlo);
    cudaGetSymbolAddress((void**)&h0hi, g_h0hi);  cudaGetSymbolAddress((void**)&h0lo, g_h0lo);
    cudaGetSymbolAddress((void**)&h1hi, g_h1hi);  cudaGetSymbolAddress((void**)&h1lo, g_h1lo);
    cudaGetSymbolAddress((void**)&wt1hi, g_wt1hi); cudaGetSymbolAddress((void**)&wt1lo, g_wt1lo);
    cudaGetSymbolAddress((void**)&wt2hi, g_wt2hi); cudaGetSymbolAddress((void**)&wt2lo, g_wt2lo);
    cudaGetSymbolAddress((void**)&wt3hi, g_wt3hi); cudaGetSymbolAddress((void**)&wt3lo, g_wt3lo);
    cudaGetSymbolAddress((void**)&wt4hi, g_wt4hi); cudaGetSymbolAddress((void**)&wt4lo, g_wt4lo);
    cudaGetSymbolAddress((void**)&hs,  g_hs);
    cudaGetSymbolAddress((void**)&hs4, g_hs4);

    // smem: A(hi+lo) 2*128*72*2 + B(hi+lo) 2*BN*72*2
    const int SMEM_BN128 = (2 * 128 * SSTR + 2 * 128 * SSTR) * 2;  // 73728
    const int SMEM_BN64  = (2 * 128 * SSTR + 2 * 64 * SSTR) * 2;   // 55296
    cudaFuncSetAttribute(mma_gemm_kernel<128, 1>, cudaFuncAttributeMaxDynamicSharedMemorySize, SMEM_BN128);
    cudaFuncSetAttribute(mma_gemm_kernel<128, 0>, cudaFuncAttributeMaxDynamicSharedMemorySize, SMEM_BN128);
    cudaFuncSetAttribute(mma_gemm_kernel<64, 0>,  cudaFuncAttributeMaxDynamicSharedMemorySize, SMEM_BN64);

    const int TB = 256;
    int nodeBlocks = (NNODES + TB - 1) / TB;
    int edgeBlocks = (NEDGES + TB - 1) / TB;

    // ---- graph build ----
    reset_kernel<<<nodeBlocks, TB>>>();
    degree_kernel<<<edgeBlocks, TB>>>(dst);
    invsqrt_kernel<<<nodeBlocks, TB>>>();
    scan_block_kernel<<<NB_SCAN, 1024>>>();
    scan_tops_kernel<<<1, 64>>>();
    scan_add_kernel<<<NB_SCAN, 1024>>>();
    fill_kernel<<<edgeBlocks, TB>>>(src, dst);

    // ---- weight prep ----
    wprep_kernel<<<(FIN * HID + TB - 1) / TB, TB>>>(W1, FIN, HID, HID, wt1hi, wt1lo);
    wprep_kernel<<<(HID * HID + TB - 1) / TB, TB>>>(W2, HID, HID, HID, wt2hi, wt2lo);
    wprep_kernel<<<(HID * HID + TB - 1) / TB, TB>>>(W3, HID, HID, HID, wt3hi, wt3lo);
    wprep_kernel<<<(HID * CPAD + TB - 1) / TB, TB>>>(W4, HID, NCLS, CPAD, wt4hi, wt4lo);

    int mBlocks = (NNODES + 127) / 128;   // 391
    dim3 gHID(mBlocks, HID / 128);        // 391 x 2
    dim3 gC(mBlocks, 1);                  // 391 x 1
    int lsmBlocks = (NNODES * 32 + TB - 1) / TB;

    // layer 1: aggregate-first, GEMM fused bias+relu+split
    agg_x_kernel<<<NNODES, FIN>>>(x);
    mma_gemm_kernel<128, 1><<<gHID, 256, SMEM_BN128>>>(
        thi, tlo, wt1hi, wt1lo, FIN, HID, nullptr, h0hi, h0lo, b1);
    // layer 2
    mma_gemm_kernel<128, 0><<<gHID, 256, SMEM_BN128>>>(
        h0hi, h0lo, wt2hi, wt2lo, HID, HID, hs, nullptr, nullptr, nullptr);
    agg_mid_kernel<<<NNODES, HID>>>(hs, b2, h1hi, h1lo);
    // layer 3
    mma_gemm_kernel<128, 0><<<gHID, 256, SMEM_BN128>>>(
        h1hi, h1lo, wt3hi, wt3lo, HID, HID, hs, nullptr, nullptr, nullptr);
    agg_mid_kernel<<<NNODES, HID>>>(hs, b3, h0hi, h0lo);
    // layer 4 + log_softmax
    mma_gemm_kernel<64, 0><<<gC, 256, SMEM_BN64>>>(
        h0hi, h0lo, wt4hi, wt4lo, HID, CPAD, hs4, nullptr, nullptr, nullptr);
    agg40_lsm_kernel<<<lsmBlocks, TB>>>(hs4, b4, out);
}

// round 6
// speedup vs baseline: 2.1338x; 1.5924x over previous
#include <cuda_runtime.h>
#include <cuda_bf16.h>
#include <cstdint>
#include <cstddef>

#define NNODES 50000
#define NEDGES 1600000
#define FIN    128
#define HID    256
#define NCLS   40
#define CPAD   64
#define NB_SCAN 49   // ceil(50000/1024)

// ================= static device scratch =================
__device__ float g_is[NNODES];
__device__ int   g_cnt[NNODES];
__device__ int   g_fill[NNODES];
__device__ int   g_rowptr[NNODES + 1];
__device__ int   g_srcs[NEDGES];
__device__ int   g_bsum[NB_SCAN];
__device__ int   g_boff[NB_SCAN];

__device__ __nv_bfloat16 g_thi[(size_t)NNODES * FIN];
__device__ __nv_bfloat16 g_tlo[(size_t)NNODES * FIN];
__device__ __nv_bfloat16 g_h0hi[(size_t)NNODES * HID];
__device__ __nv_bfloat16 g_h0lo[(size_t)NNODES * HID];
__device__ __nv_bfloat16 g_h1hi[(size_t)NNODES * HID];
__device__ __nv_bfloat16 g_h1lo[(size_t)NNODES * HID];
__device__ float g_hs[(size_t)NNODES * HID];
__device__ float g_hs4[(size_t)NNODES * CPAD];

// weights transposed+split: Wt[n][k] row-major [Npad][K]
__device__ __nv_bfloat16 g_wt1hi[HID * FIN],  g_wt1lo[HID * FIN];
__device__ __nv_bfloat16 g_wt2hi[HID * HID],  g_wt2lo[HID * HID];
__device__ __nv_bfloat16 g_wt3hi[HID * HID],  g_wt3lo[HID * HID];
__device__ __nv_bfloat16 g_wt4hi[CPAD * HID], g_wt4lo[CPAD * HID];

// ================= PTX helpers (base compute_103-legal only) =================
__device__ __forceinline__ uint32_t smem_u32(const void* p) {
    uint32_t a;
    asm("{ .reg .u64 t; cvta.to.shared.u64 t, %1; cvt.u32.u64 %0, t; }" : "=r"(a) : "l"(p));
    return a;
}
__device__ __forceinline__ void ldsm_x4(uint32_t& r0, uint32_t& r1, uint32_t& r2, uint32_t& r3,
                                        uint32_t addr) {
    asm volatile("ldmatrix.sync.aligned.m8n8.x4.shared.b16 {%0,%1,%2,%3}, [%4];"
                 : "=r"(r0), "=r"(r1), "=r"(r2), "=r"(r3) : "r"(addr));
}
__device__ __forceinline__ void mma16816(float& c0, float& c1, float& c2, float& c3,
                                         uint32_t a0, uint32_t a1, uint32_t a2, uint32_t a3,
                                         uint32_t b0, uint32_t b1) {
    asm volatile("mma.sync.aligned.m16n8k16.row.col.f32.bf16.bf16.f32 "
                 "{%0,%1,%2,%3}, {%4,%5,%6,%7}, {%8,%9}, {%0,%1,%2,%3};"
                 : "+f"(c0), "+f"(c1), "+f"(c2), "+f"(c3)
                 : "r"(a0), "r"(a1), "r"(a2), "r"(a3), "r"(b0), "r"(b1));
}
__device__ __forceinline__ void cp_async16(uint32_t dst, const void* src, int sz) {
    asm volatile("cp.async.cg.shared.global [%0], [%1], 16, %2;"
                 :: "r"(dst), "l"(src), "r"(sz));
}
#define CP_COMMIT() asm volatile("cp.async.commit_group;")

// ================= graph preprocessing =================
__global__ void degree_kernel(const int* __restrict__ dst) {
    int e = blockIdx.x * blockDim.x + threadIdx.x;
    if (e < NEDGES) atomicAdd(&g_cnt[dst[e]], 1);
}
__global__ __launch_bounds__(1024) void scan_block_kernel() {   // also computes g_is
    __shared__ int ws[32];
    int t = threadIdx.x, b = blockIdx.x;
    int i = b * 1024 + t;
    int v = (i < NNODES) ? g_cnt[i] : 0;
    if (i < NNODES) g_is[i] = rsqrtf((float)v + 1.0f);
    int lane = t & 31, w = t >> 5;
    int x = v;
#pragma unroll
    for (int off = 1; off < 32; off <<= 1) {
        int y = __shfl_up_sync(0xffffffffu, x, off);
        if (lane >= off) x += y;
    }
    if (lane == 31) ws[w] = x;
    __syncthreads();
    if (w == 0) {
        int s = ws[lane];
#pragma unroll
        for (int off = 1; off < 32; off <<= 1) {
            int y = __shfl_up_sync(0xffffffffu, s, off);
            if (lane >= off) s += y;
        }
        ws[lane] = s;
    }
    __syncthreads();
    int incl = x + (w ? ws[w - 1] : 0);
    if (i < NNODES) g_rowptr[i] = incl - v;
    if (t == 1023) g_bsum[b] = incl;
}
__global__ void scan_tops_kernel() {
    __shared__ int s[64];
    int t = threadIdx.x;
    int v = (t < NB_SCAN) ? g_bsum[t] : 0;
    s[t] = v;
    __syncthreads();
    for (int off = 1; off < 64; off <<= 1) {
        int y = (t >= off) ? s[t - off] : 0;
        __syncthreads();
        s[t] += y;
        __syncthreads();
    }
    if (t < NB_SCAN) g_boff[t] = s[t] - v;
    if (t == NB_SCAN - 1) g_rowptr[NNODES] = s[t];
}
__global__ __launch_bounds__(1024) void scan_add_kernel() {
    int i = blockIdx.x * 1024 + threadIdx.x;
    if (i < NNODES) g_rowptr[i] += g_boff[blockIdx.x];
}
__global__ void fill_kernel(const int* __restrict__ src, const int* __restrict__ dst) {
    int e = blockIdx.x * blockDim.x + threadIdx.x;
    if (e < NEDGES) {
        int d = dst[e];
        int p = atomicAdd(&g_fill[d], 1);
        g_srcs[g_rowptr[d] + p] = src[e];
    }
}
__global__ void wprep_kernel(const float* __restrict__ W, int K, int Nw, int Npad,
                             __nv_bfloat16* __restrict__ dhi, __nv_bfloat16* __restrict__ dlo) {
    int i = blockIdx.x * blockDim.x + threadIdx.x;
    if (i < K * Npad) {
        int n = i / K, k = i % K;
        float v = (n < Nw) ? W[k * Nw + n] : 0.0f;
        __nv_bfloat16 h = __float2bfloat16(v);
        dhi[i] = h;
        dlo[i] = __float2bfloat16(v - __bfloat162float(h));
    }
}

// ================= aggregation kernels (float4) =================
// layer-1 aggregate-first: warp per node (32 thr x float4 = 128 feats)
__global__ __launch_bounds__(256) void agg_x_kernel(const float4* __restrict__ x) {
    int n = blockIdx.x * 8 + (threadIdx.x >> 5);
    int t = threadIdx.x & 31;
    if (n >= NNODES) return;
    int beg = g_rowptr[n], end = g_rowptr[n + 1];
    float isn = g_is[n];
    float4 s = x[(size_t)n * 32 + t];
    float a0 = isn * s.x, a1 = isn * s.y, a2 = isn * s.z, a3 = isn * s.w;
    float c0 = 0.f, c1 = 0.f, c2 = 0.f, c3 = 0.f;
    int e = beg;
    for (; e + 2 <= end; e += 2) {
        int s0 = g_srcs[e], s1 = g_srcs[e + 1];
        float w0 = g_is[s0], w1 = g_is[s1];
        float4 u = x[(size_t)s0 * 32 + t];
        float4 v = x[(size_t)s1 * 32 + t];
        a0 += w0 * u.x; a1 += w0 * u.y; a2 += w0 * u.z; a3 += w0 * u.w;
        c0 += w1 * v.x; c1 += w1 * v.y; c2 += w1 * v.z; c3 += w1 * v.w;
    }
    if (e < end) {
        int s0 = g_srcs[e]; float w0 = g_is[s0];
        float4 u = x[(size_t)s0 * 32 + t];
        a0 += w0 * u.x; a1 += w0 * u.y; a2 += w0 * u.z; a3 += w0 * u.w;
    }
    float vv[4] = { isn * (a0 + c0), isn * (a1 + c1), isn * (a2 + c2), isn * (a3 + c3) };
    unsigned short hh[4], ll[4];
#pragma unroll
    for (int k = 0; k < 4; k++) {
        __nv_bfloat16 h = __float2bfloat16(vv[k]);
        __nv_bfloat16 l = __float2bfloat16(vv[k] - __bfloat162float(h));
        hh[k] = *reinterpret_cast<unsigned short*>(&h);
        ll[k] = *reinterpret_cast<unsigned short*>(&l);
    }
    *(uint2*)(g_thi + (size_t)n * FIN + 4 * t) = *(uint2*)hh;
    *(uint2*)(g_tlo + (size_t)n * FIN + 4 * t) = *(uint2*)ll;
}
// mid layers: 64 threads per node (64 x float4 = 256 feats)
__global__ __launch_bounds__(256) void agg_mid_kernel(
    const float4* __restrict__ hs, const float* __restrict__ bias,
    __nv_bfloat16* __restrict__ ohi, __nv_bfloat16* __restrict__ olo) {
    int n = blockIdx.x * 4 + (threadIdx.x >> 6);
    int t = threadIdx.x & 63;
    if (n >= NNODES) return;
    int beg = g_rowptr[n], end = g_rowptr[n + 1];
    float4 s = hs[(size_t)n * 64 + t];
    float a0 = s.x, a1 = s.y, a2 = s.z, a3 = s.w;
    float c0 = 0.f, c1 = 0.f, c2 = 0.f, c3 = 0.f;
    int e = beg;
    for (; e + 2 <= end; e += 2) {
        float4 u = hs[(size_t)g_srcs[e] * 64 + t];
        float4 v = hs[(size_t)g_srcs[e + 1] * 64 + t];
        a0 += u.x; a1 += u.y; a2 += u.z; a3 += u.w;
        c0 += v.x; c1 += v.y; c2 += v.z; c3 += v.w;
    }
    if (e < end) {
        float4 u = hs[(size_t)g_srcs[e] * 64 + t];
        a0 += u.x; a1 += u.y; a2 += u.z; a3 += u.w;
    }
    float isn = g_is[n];
    float4 bb = *(const float4*)(bias + 4 * t);
    float vv[4] = { fmaxf(isn * (a0 + c0) + bb.x, 0.f), fmaxf(isn * (a1 + c1) + bb.y, 0.f),
                    fmaxf(isn * (a2 + c2) + bb.z, 0.f), fmaxf(isn * (a3 + c3) + bb.w, 0.f) };
    unsigned short hh[4], ll[4];
#pragma unroll
    for (int k = 0; k < 4; k++) {
        __nv_bfloat16 h = __float2bfloat16(vv[k]);
        __nv_bfloat16 l = __float2bfloat16(vv[k] - __bfloat162float(h));
        hh[k] = *reinterpret_cast<unsigned short*>(&h);
        ll[k] = *reinterpret_cast<unsigned short*>(&l);
    }
    *(uint2*)(ohi + (size_t)n * HID + 4 * t) = *(uint2*)hh;
    *(uint2*)(olo + (size_t)n * HID + 4 * t) = *(uint2*)ll;
}
// layer 4: 16 threads per node (16 x float4 = 64 padded cols) + log_softmax
__global__ __launch_bounds__(256) void agg40_lsm_kernel(
    const float4* __restrict__ hs4, const float* __restrict__ b4, float* __restrict__ out) {
    int n = blockIdx.x * 16 + (threadIdx.x >> 4);
    int t = threadIdx.x & 15;
    if (n >= NNODES) return;
    int beg = g_rowptr[n], end = g_rowptr[n + 1];
    float4 s = hs4[(size_t)n * 16 + t];
    float a0 = s.x, a1 = s.y, a2 = s.z, a3 = s.w;
    float c0 = 0.f, c1 = 0.f, c2 = 0.f, c3 = 0.f;
    int e = beg;
    for (; e + 2 <= end; e += 2) {
        float4 u = hs4[(size_t)g_srcs[e] * 16 + t];
        float4 v = hs4[(size_t)g_srcs[e + 1] * 16 + t];
        a0 += u.x; a1 += u.y; a2 += u.z; a3 += u.w;
        c0 += v.x; c1 += v.y; c2 += v.z; c3 += v.w;
    }
    if (e < end) {
        float4 u = hs4[(size_t)g_srcs[e] * 16 + t];
        a0 += u.x; a1 += u.y; a2 += u.z; a3 += u.w;
    }
    float sc = g_is[n];
    float sums[4] = { a0 + c0, a1 + c1, a2 + c2, a3 + c3 };
    int col0 = 4 * t;
    float v[4];
#pragma unroll
    for (int k = 0; k < 4; k++)
        v[k] = (col0 + k < NCLS) ? (sc * sums[k] + b4[col0 + k]) : -1e30f;
    float m = fmaxf(fmaxf(v[0], v[1]), fmaxf(v[2], v[3]));
#pragma unroll
    for (int off = 8; off; off >>= 1) m = fmaxf(m, __shfl_xor_sync(0xffffffffu, m, off));
    float se = 0.f;
#pragma unroll
    for (int k = 0; k < 4; k++) se += (col0 + k < NCLS) ? __expf(v[k] - m) : 0.f;
#pragma unroll
    for (int off = 8; off; off >>= 1) se += __shfl_xor_sync(0xffffffffu, se, off);
    float lse = m + __logf(se);
    if (t < 10) {
        float4 o;
        o.x = v[0] - lse; o.y = v[1] - lse; o.z = v[2] - lse; o.w = v[3] - lse;
        *(float4*)(out + (size_t)n * NCLS + col0) = o;
    }
}

// ================= HMMA bf16x2-split GEMM, cp.async pipelined =================
// C[M, NT] = (Ahi+Alo) @ (Bhi+Blo)^T (lo*lo dropped), fp32 accum.
// B resident in smem for full K; A double-buffered in 64-wide K chunks.
// MODE 0: Cf = D * g_is[m]; MODE 1: relu(D + bias[n]) -> Chi/Clo.
#define ASTR 72    // A smem row stride (bf16): conflict-free for ldmatrix

template <int KT, int BN_T, int MODE>
__global__ __launch_bounds__(256) void mma_gemm_kernel(
    const __nv_bfloat16* __restrict__ Ahi, const __nv_bfloat16* __restrict__ Alo,
    const __nv_bfloat16* __restrict__ Bhi, const __nv_bfloat16* __restrict__ Blo,
    int NT,
    float* __restrict__ Cf,
    __nv_bfloat16* __restrict__ Chi, __nv_bfloat16* __restrict__ Clo,
    const float* __restrict__ bias)
{
    extern __shared__ __nv_bfloat16 sm[];
    constexpr int NCH = KT / 64;
    constexpr int BSTR = KT + 8;               // B smem row stride (conflict-free)
    constexpr int AHALF_B = 128 * ASTR * 2;    // 18432 bytes (one of hi/lo per stage)
    constexpr int ASTG_B  = 2 * AHALF_B;       // 36864 bytes per stage
    constexpr int ABUF_B  = 2 * ASTG_B;        // 73728 bytes (2 stages)
    constexpr int BHALF_B = BN_T * BSTR * 2;

    const int tid = threadIdx.x;
    const int lane = tid & 31;
    const int wid = tid >> 5;
    const int wm = wid & 3;
    const int wn = wid >> 2;
    constexpr int WN = BN_T / 2;
    constexpr int NTILES = WN / 8;

    const int row0 = blockIdx.x * 128;
    const int col0 = blockIdx.y * BN_T;

    const uint32_t uS = smem_u32(sm);
    const uint32_t uB = uS + ABUF_B;

    auto loadA = [&](int c) {
        int k0 = c * 64;
        uint32_t ab = uS + (c & 1) * ASTG_B;
#pragma unroll
        for (int it = 0; it < 4; it++) {
            int idx = tid + it * 256;
            int r = idx >> 3, q = idx & 7;
            int gr = row0 + r;
            int sz = (gr < NNODES) ? 16 : 0;
            uint32_t d = ab + (uint32_t)(r * ASTR + q * 8) * 2;
            cp_async16(d,           Ahi + (size_t)gr * KT + k0 + q * 8, sz);
            cp_async16(d + AHALF_B, Alo + (size_t)gr * KT + k0 + q * 8, sz);
        }
    };

    // B resident load (full K) + first A chunk, one commit group
    {
        constexpr int BUNITS = BN_T * KT / 8;
        for (int u = tid; u < BUNITS; u += 256) {
            int n = u / (KT / 8), q = u % (KT / 8);
            uint32_t d = uB + (uint32_t)(n * BSTR + q * 8) * 2;
            cp_async16(d,           Bhi + (size_t)(col0 + n) * KT + q * 8, 16);
            cp_async16(d + BHALF_B, Blo + (size_t)(col0 + n) * KT + q * 8, 16);
        }
        loadA(0);
        CP_COMMIT();
    }

    float acc[2][NTILES][4];
#pragma unroll
    for (int i = 0; i < 2; i++)
#pragma unroll
        for (int j = 0; j < NTILES; j++)
#pragma unroll
            for (int q = 0; q < 4; q++) acc[i][j][q] = 0.0f;

    const int a_r = (lane & 7) + ((lane >> 3) & 1) * 8;
    const int a_k = (lane >> 4) * 8;
    const int b_n = (lane & 7) + ((lane >> 4) & 1) * 8;
    const int b_k = ((lane >> 3) & 1) * 8;

#pragma unroll
    for (int c = 0; c < NCH; c++) {
        if (c + 1 < NCH) {
            loadA(c + 1);
            CP_COMMIT();
            asm volatile("cp.async.wait_group 1;");
        } else {
            asm volatile("cp.async.wait_group 0;");
        }
        __syncthreads();

        uint32_t abh = uS + (c & 1) * ASTG_B;
        uint32_t abl = abh + AHALF_B;
#pragma unroll
        for (int ks = 0; ks < 4; ks++) {
            uint32_t ah[2][4], al[2][4];
#pragma unroll
            for (int mt = 0; mt < 2; mt++) {
                uint32_t off = (uint32_t)(((wm * 32 + mt * 16 + a_r) * ASTR + ks * 16 + a_k) * 2);
                ldsm_x4(ah[mt][0], ah[mt][1], ah[mt][2], ah[mt][3], abh + off);
                ldsm_x4(al[mt][0], al[mt][1], al[mt][2], al[mt][3], abl + off);
            }
            uint32_t bh[NTILES][2], bl[NTILES][2];
#pragma unroll
            for (int nb = 0; nb < NTILES / 2; nb++) {
                uint32_t off = (uint32_t)(((wn * WN + nb * 16 + b_n) * BSTR + c * 64 + ks * 16 + b_k) * 2);
                uint32_t r0, r1, r2, r3;
                ldsm_x4(r0, r1, r2, r3, uB + off);
                bh[nb * 2][0] = r0; bh[nb * 2][1] = r1;
                bh[nb * 2 + 1][0] = r2; bh[nb * 2 + 1][1] = r3;
                ldsm_x4(r0, r1, r2, r3, uB + BHALF_B + off);
                bl[nb * 2][0] = r0; bl[nb * 2][1] = r1;
                bl[nb * 2 + 1][0] = r2; bl[nb * 2 + 1][1] = r3;
            }
#pragma unroll
            for (int mt = 0; mt < 2; mt++)
#pragma unroll
                for (int nt = 0; nt < NTILES; nt++) {
                    mma16816(acc[mt][nt][0], acc[mt][nt][1], acc[mt][nt][2], acc[mt][nt][3],
                             ah[mt][0], ah[mt][1], ah[mt][2], ah[mt][3], bh[nt][0], bh[nt][1]);
                    mma16816(acc[mt][nt][0], acc[mt][nt][1], acc[mt][nt][2], acc[mt][nt][3],
                             ah[mt][0], ah[mt][1], ah[mt][2], ah[mt][3], bl[nt][0], bl[nt][1]);
                    mma16816(acc[mt][nt][0], acc[mt][nt][1], acc[mt][nt][2], acc[mt][nt][3],
                             al[mt][0], al[mt][1], al[mt][2], al[mt][3], bh[nt][0], bh[nt][1]);
                }
        }
        __syncthreads();
    }

    // ---- epilogue ----
    const int rbase = row0 + wm * 32 + (lane >> 2);
    const int cbase = col0 + wn * WN + ((lane & 3) * 2);
#pragma unroll
    for (int mt = 0; mt < 2; mt++) {
#pragma unroll
        for (int half = 0; half < 2; half++) {
            int gr = rbase + mt * 16 + half * 8;
            if (gr < NNODES) {
                if (MODE == 0) {
                    float s = g_is[gr];
#pragma unroll
                    for (int nt = 0; nt < NTILES; nt++) {
                        float2 v;
                        v.x = acc[mt][nt][half * 2 + 0] * s;
                        v.y = acc[mt][nt][half * 2 + 1] * s;
                        *(float2*)(Cf + (size_t)gr * NT + cbase + nt * 8) = v;
                    }
                } else {
#pragma unroll
                    for (int nt = 0; nt < NTILES; nt++) {
                        int c = cbase + nt * 8;
                        float v0 = fmaxf(acc[mt][nt][half * 2 + 0] + bias[c], 0.0f);
                        float v1 = fmaxf(acc[mt][nt][half * 2 + 1] + bias[c + 1], 0.0f);
                        __nv_bfloat16 h0 = __float2bfloat16(v0);
                        __nv_bfloat16 h1 = __float2bfloat16(v1);
                        __nv_bfloat162 hp; hp.x = h0; hp.y = h1;
                        __nv_bfloat162 lp;
                        lp.x = __float2bfloat16(v0 - __bfloat162float(h0));
                        lp.y = __float2bfloat16(v1 - __bfloat162float(h1));
                        *(__nv_bfloat162*)(Chi + (size_t)gr * NT + c) = hp;
                        *(__nv_bfloat162*)(Clo + (size_t)gr * NT + c) = lp;
                    }
                }
            }
        }
    }
}

// ================= launch =================
extern "C" void kernel_launch(void* const* d_in, const int* in_sizes, int n_in,
                              void* d_out, int out_size)
{
    const float* x  = (const float*)d_in[0];
    const int*   ei = (const int*)  d_in[1];
    const float* W1 = (const float*)d_in[2];
    const float* b1 = (const float*)d_in[3];
    const float* W2 = (const float*)d_in[4];
    const float* b2 = (const float*)d_in[5];
    const float* W3 = (const float*)d_in[6];
    const float* b3 = (const float*)d_in[7];
    const float* W4 = (const float*)d_in[8];
    const float* b4 = (const float*)d_in[9];
    float* out = (float*)d_out;

    const int* src = ei;
    const int* dst = ei + NEDGES;

    __nv_bfloat16 *thi, *tlo, *h0hi, *h0lo, *h1hi, *h1lo;
    __nv_bfloat16 *wt1hi, *wt1lo, *wt2hi, *wt2lo, *wt3hi, *wt3lo, *wt4hi, *wt4lo;
    float *hs, *hs4;
    int *cntp, *fillp;
    cudaGetSymbolAddress((void**)&thi,  g_thi);   cudaGetSymbolAddress((void**)&tlo,  g_tlo);
    cudaGetSymbolAddress((void**)&h0hi, g_h0hi);  cudaGetSymbolAddress((void**)&h0lo, g_h0lo);
    cudaGetSymbolAddress((void**)&h1hi, g_h1hi);  cudaGetSymbolAddress((void**)&h1lo, g_h1lo);
    cudaGetSymbolAddress((void**)&wt1hi, g_wt1hi); cudaGetSymbolAddress((void**)&wt1lo, g_wt1lo);
    cudaGetSymbolAddress((void**)&wt2hi, g_wt2hi); cudaGetSymbolAddress((void**)&wt2lo, g_wt2lo);
    cudaGetSymbolAddress((void**)&wt3hi, g_wt3hi); cudaGetSymbolAddress((void**)&wt3lo, g_wt3lo);
    cudaGetSymbolAddress((void**)&wt4hi, g_wt4hi); cudaGetSymbolAddress((void**)&wt4lo, g_wt4lo);
    cudaGetSymbolAddress((void**)&hs,  g_hs);
    cudaGetSymbolAddress((void**)&hs4, g_hs4);
    cudaGetSymbolAddress((void**)&cntp, g_cnt);
    cudaGetSymbolAddress((void**)&fillp, g_fill);

    // smem sizes: A double-buffer 73728B + B-resident 2*BN*(K+8)*2B
    const int SMEM_L1 = 73728 + 2 * 128 * (128 + 8) * 2;  // 143360
    const int SMEM_L2 = 73728 + 2 * 128 * (256 + 8) * 2;  // 208896
    const int SMEM_L4 = 73728 + 2 * 64  * (256 + 8) * 2;  // 141312
    cudaFuncSetAttribute(mma_gemm_kernel<128, 128, 1>, cudaFuncAttributeMaxDynamicSharedMemorySize, SMEM_L1);
    cudaFuncSetAttribute(mma_gemm_kernel<256, 128, 0>, cudaFuncAttributeMaxDynamicSharedMemorySize, SMEM_L2);
    cudaFuncSetAttribute(mma_gemm_kernel<256, 64, 0>,  cudaFuncAttributeMaxDynamicSharedMemorySize, SMEM_L4);

    const int TB = 256;
    int edgeBlocks = (NEDGES + TB - 1) / TB;

    // ---- graph build ----
    cudaMemsetAsync(cntp, 0, NNODES * sizeof(int));
    cudaMemsetAsync(fillp, 0, NNODES * sizeof(int));
    degree_kernel<<<edgeBlocks, TB>>>(dst);
    scan_block_kernel<<<NB_SCAN, 1024>>>();
    scan_tops_kernel<<<1, 64>>>();
    scan_add_kernel<<<NB_SCAN, 1024>>>();
    fill_kernel<<<edgeBlocks, TB>>>(src, dst);

    // ---- weight prep ----
    wprep_kernel<<<(FIN * HID + TB - 1) / TB, TB>>>(W1, FIN, HID, HID, wt1hi, wt1lo);
    wprep_kernel<<<(HID * HID + TB - 1) / TB, TB>>>(W2, HID, HID, HID, wt2hi, wt2lo);
    wprep_kernel<<<(HID * HID + TB - 1) / TB, TB>>>(W3, HID, HID, HID, wt3hi, wt3lo);
    wprep_kernel<<<(HID * CPAD + TB - 1) / TB, TB>>>(W4, HID, NCLS, CPAD, wt4hi, wt4lo);

    int mBlocks = (NNODES + 127) / 128;          // 391
    dim3 gHID(mBlocks, 2);                       // BN=128 x 2 = 256 cols
    dim3 gC(mBlocks, 1);                         // BN=64
    int axBlocks  = (NNODES + 7) / 8;            // 6250
    int amBlocks  = (NNODES + 3) / 4;            // 12500
    int a40Blocks = (NNODES + 15) / 16;          // 3125

    // layer 1: aggregate-first, GEMM fused bias+relu+split
    agg_x_kernel<<<axBlocks, TB>>>((const float4*)x);
    mma_gemm_kernel<128, 128, 1><<<gHID, 256, SMEM_L1>>>(
        thi, tlo, wt1hi, wt1lo, HID, nullptr, h0hi, h0lo, b1);
    // layer 2
    mma_gemm_kernel<256, 128, 0><<<gHID, 256, SMEM_L2>>>(
        h0hi, h0lo, wt2hi, wt2lo, HID, hs, nullptr, nullptr, nullptr);
    agg_mid_kernel<<<amBlocks, TB>>>((const float4*)hs, b2, h1hi, h1lo);
    // layer 3
    mma_gemm_kernel<256, 128, 0><<<gHID, 256, SMEM_L2>>>(
        h1hi, h1lo, wt3hi, wt3lo, HID, hs, nullptr, nullptr, nullptr);
    agg_mid_kernel<<<amBlocks, TB>>>((const float4*)hs, b3, h0hi, h0lo);
    // layer 4 + log_softmax
    mma_gemm_kernel<256, 64, 0><<<gC, 256, SMEM_L4>>>(
        h0hi, h0lo, wt4hi, wt4lo, CPAD, hs4, nullptr, nullptr, nullptr);
    agg40_lsm_kernel<<<a40Blocks, TB>>>((const float4*)hs4, b4, out);
}

// round 9
// speedup vs baseline: 2.5153x; 1.1788x over previous
#include <cuda_runtime.h>
#include <cuda_bf16.h>
#include <cuda_fp16.h>
#include <cstdint>
#include <cstddef>

#define NNODES 50000
#define NEDGES 1600000
#define FIN    128
#define HID    256
#define NCLS   40
#define CPAD   64
#define NB_SCAN 49   // ceil(50000/1024)

// ================= static device scratch =================
__device__ float g_is[NNODES];
__device__ int   g_cnt[NNODES];
__device__ int   g_fill[NNODES];
__device__ int   g_rowptr[NNODES + 1];
__device__ int   g_srcs[NEDGES];
__device__ int   g_bsum[NB_SCAN];
__device__ int   g_boff[NB_SCAN];

__device__ __half g_xs[(size_t)NNODES * FIN];     // is[n]*x[n] in fp16
__device__ __half g_hsh[(size_t)NNODES * HID];    // GEMM out (scaled) fp16 gather table
__device__ __half g_hs4h[(size_t)NNODES * CPAD];  // layer-4 GEMM out fp16

__device__ __nv_bfloat16 g_thi[(size_t)NNODES * FIN];
__device__ __nv_bfloat16 g_tlo[(size_t)NNODES * FIN];
__device__ __nv_bfloat16 g_h0hi[(size_t)NNODES * HID];
__device__ __nv_bfloat16 g_h0lo[(size_t)NNODES * HID];
__device__ __nv_bfloat16 g_h1hi[(size_t)NNODES * HID];
__device__ __nv_bfloat16 g_h1lo[(size_t)NNODES * HID];

// weights transposed+split: Wt[n][k] row-major [Npad][K]
__device__ __nv_bfloat16 g_wt1hi[HID * FIN],  g_wt1lo[HID * FIN];
__device__ __nv_bfloat16 g_wt2hi[HID * HID],  g_wt2lo[HID * HID];
__device__ __nv_bfloat16 g_wt3hi[HID * HID],  g_wt3lo[HID * HID];
__device__ __nv_bfloat16 g_wt4hi[CPAD * HID], g_wt4lo[CPAD * HID];

// ================= PTX helpers (base compute_103-legal only) =================
__device__ __forceinline__ uint32_t smem_u32(const void* p) {
    uint32_t a;
    asm("{ .reg .u64 t; cvta.to.shared.u64 t, %1; cvt.u32.u64 %0, t; }" : "=r"(a) : "l"(p));
    return a;
}
__device__ __forceinline__ void ldsm_x4(uint32_t& r0, uint32_t& r1, uint32_t& r2, uint32_t& r3,
                                        uint32_t addr) {
    asm volatile("ldmatrix.sync.aligned.m8n8.x4.shared.b16 {%0,%1,%2,%3}, [%4];"
                 : "=r"(r0), "=r"(r1), "=r"(r2), "=r"(r3) : "r"(addr));
}
__device__ __forceinline__ void mma16816(float& c0, float& c1, float& c2, float& c3,
                                         uint32_t a0, uint32_t a1, uint32_t a2, uint32_t a3,
                                         uint32_t b0, uint32_t b1) {
    asm volatile("mma.sync.aligned.m16n8k16.row.col.f32.bf16.bf16.f32 "
                 "{%0,%1,%2,%3}, {%4,%5,%6,%7}, {%8,%9}, {%0,%1,%2,%3};"
                 : "+f"(c0), "+f"(c1), "+f"(c2), "+f"(c3)
                 : "r"(a0), "r"(a1), "r"(a2), "r"(a3), "r"(b0), "r"(b1));
}
__device__ __forceinline__ void cp_async16(uint32_t dst, const void* src, int sz) {
    asm volatile("cp.async.cg.shared.global [%0], [%1], 16, %2;"
                 :: "r"(dst), "l"(src), "r"(sz));
}
#define CP_COMMIT() asm volatile("cp.async.commit_group;")

__device__ __forceinline__ void acc8(float* a, uint4 v) {
    __half2* h = reinterpret_cast<__half2*>(&v);
#pragma unroll
    for (int i = 0; i < 4; i++) {
        float2 f = __half22float2(h[i]);
        a[2 * i]     += f.x;
        a[2 * i + 1] += f.y;
    }
}
__device__ __forceinline__ void acc4(float* a, uint2 v) {
    __half2* h = reinterpret_cast<__half2*>(&v);
#pragma unroll
    for (int i = 0; i < 2; i++) {
        float2 f = __half22float2(h[i]);
        a[2 * i]     += f.x;
        a[2 * i + 1] += f.y;
    }
}

// ================= graph preprocessing =================
__global__ void degree_kernel(const int* __restrict__ dst) {
    int e = blockIdx.x * blockDim.x + threadIdx.x;
    if (e < NEDGES) atomicAdd(&g_cnt[dst[e]], 1);
}
__global__ __launch_bounds__(1024) void scan_block_kernel() {   // also computes g_is
    __shared__ int ws[32];
    int t = threadIdx.x, b = blockIdx.x;
    int i = b * 1024 + t;
    int v = (i < NNODES) ? g_cnt[i] : 0;
    if (i < NNODES) g_is[i] = rsqrtf((float)v + 1.0f);
    int lane = t & 31, w = t >> 5;
    int x = v;
#pragma unroll
    for (int off = 1; off < 32; off <<= 1) {
        int y = __shfl_up_sync(0xffffffffu, x, off);
        if (lane >= off) x += y;
    }
    if (lane == 31) ws[w] = x;
    __syncthreads();
    if (w == 0) {
        int s = ws[lane];
#pragma unroll
        for (int off = 1; off < 32; off <<= 1) {
            int y = __shfl_up_sync(0xffffffffu, s, off);
            if (lane >= off) s += y;
        }
        ws[lane] = s;
    }
    __syncthreads();
    int incl = x + (w ? ws[w - 1] : 0);
    if (i < NNODES) g_rowptr[i] = incl - v;
    if (t == 1023) g_bsum[b] = incl;
}
__global__ void scan_tops_kernel() {
    __shared__ int s[64];
    int t = threadIdx.x;
    int v = (t < NB_SCAN) ? g_bsum[t] : 0;
    s[t] = v;
    __syncthreads();
    for (int off = 1; off < 64; off <<= 1) {
        int y = (t >= off) ? s[t - off] : 0;
        __syncthreads();
        s[t] += y;
        __syncthreads();
    }
    if (t < NB_SCAN) g_boff[t] = s[t] - v;
    if (t == NB_SCAN - 1) g_rowptr[NNODES] = s[t];
}
__global__ __launch_bounds__(1024) void scan_add_kernel() {
    int i = blockIdx.x * 1024 + threadIdx.x;
    if (i < NNODES) g_rowptr[i] += g_boff[blockIdx.x];
}
__global__ void fill_kernel(const int* __restrict__ src, const int* __restrict__ dst) {
    int e = blockIdx.x * blockDim.x + threadIdx.x;
    if (e < NEDGES) {
        int d = dst[e];
        int p = atomicAdd(&g_fill[d], 1);
        g_srcs[g_rowptr[d] + p] = src[e];
    }
}
__global__ void wprep_kernel(const float* __restrict__ W, int K, int Nw, int Npad,
                             __nv_bfloat16* __restrict__ dhi, __nv_bfloat16* __restrict__ dlo) {
    int i = blockIdx.x * blockDim.x + threadIdx.x;
    if (i < K * Npad) {
        int n = i / K, k = i % K;
        float v = (n < Nw) ? W[k * Nw + n] : 0.0f;
        __nv_bfloat16 h = __float2bfloat16(v);
        dhi[i] = h;
        dlo[i] = __float2bfloat16(v - __bfloat162float(h));
    }
}
// xs[n][f] = is[n] * x[n][f]  (fp16)
__global__ void xprep_kernel(const float4* __restrict__ x) {
    int i = blockIdx.x * blockDim.x + threadIdx.x;   // one float4 (4 feats)
    if (i < NNODES * FIN / 4) {
        int n = i >> 5;                              // 32 float4 per node
        float isn = g_is[n];
        float4 v = x[i];
        __half2* o = reinterpret_cast<__half2*>(g_xs) + 2 * i;
        o[0] = __floats2half2_rn(isn * v.x, isn * v.y);
        o[1] = __floats2half2_rn(isn * v.z, isn * v.w);
    }
}

// ================= aggregation kernels (fp16 gather, fp32 accum) =================
// layer-1: warp per node; t[n] = is[n]*(sum_src xs[src] + xs[n]) -> bf16 hi/lo
__global__ __launch_bounds__(256) void agg_x_kernel() {
    int n = blockIdx.x * 8 + (threadIdx.x >> 5);
    int t = threadIdx.x & 31;                // 4 feats per thread
    if (n >= NNODES) return;
    const uint2* xr = reinterpret_cast<const uint2*>(g_xs);
    int beg = g_rowptr[n], end = g_rowptr[n + 1];
    float a[4] = {0.f, 0.f, 0.f, 0.f};
    acc4(a, xr[(size_t)n * 32 + t]);         // self (xs already is-scaled)
    int e = beg;
    for (; e + 2 <= end; e += 2) {
        uint2 u = xr[(size_t)g_srcs[e] * 32 + t];
        uint2 v = xr[(size_t)g_srcs[e + 1] * 32 + t];
        acc4(a, u); acc4(a, v);
    }
    if (e < end) acc4(a, xr[(size_t)g_srcs[e] * 32 + t]);
    float isn = g_is[n];
    unsigned short hh[4], ll[4];
#pragma unroll
    for (int k = 0; k < 4; k++) {
        float v = isn * a[k];
        __nv_bfloat16 h = __float2bfloat16(v);
        __nv_bfloat16 l = __float2bfloat16(v - __bfloat162float(h));
        hh[k] = *reinterpret_cast<unsigned short*>(&h);
        ll[k] = *reinterpret_cast<unsigned short*>(&l);
    }
    *(uint2*)(g_thi + (size_t)n * FIN + 4 * t) = *(uint2*)hh;
    *(uint2*)(g_tlo + (size_t)n * FIN + 4 * t) = *(uint2*)ll;
}
// mid layers: warp per node, 8 feats per thread (uint4 = 8 halfs)
__global__ __launch_bounds__(256) void agg_mid_kernel(
    const __half* __restrict__ hs, const float* __restrict__ bias,
    __nv_bfloat16* __restrict__ ohi, __nv_bfloat16* __restrict__ olo) {
    int n = blockIdx.x * 8 + (threadIdx.x >> 5);
    int t = threadIdx.x & 31;                // feats [8t, 8t+8)
    if (n >= NNODES) return;
    const uint4* hr = reinterpret_cast<const uint4*>(hs);
    int beg = g_rowptr[n], end = g_rowptr[n + 1];
    float a[8] = {0.f, 0.f, 0.f, 0.f, 0.f, 0.f, 0.f, 0.f};
    acc8(a, hr[(size_t)n * 32 + t]);         // self
    int e = beg;
    for (; e + 2 <= end; e += 2) {
        uint4 u = hr[(size_t)g_srcs[e] * 32 + t];
        uint4 v = hr[(size_t)g_srcs[e + 1] * 32 + t];
        acc8(a, u); acc8(a, v);
    }
    if (e < end) acc8(a, hr[(size_t)g_srcs[e] * 32 + t]);
    float isn = g_is[n];
    unsigned short hh[8], ll[8];
#pragma unroll
    for (int k = 0; k < 8; k++) {
        float v = fmaxf(isn * a[k] + bias[8 * t + k], 0.0f);
        __nv_bfloat16 h = __float2bfloat16(v);
        __nv_bfloat16 l = __float2bfloat16(v - __bfloat162float(h));
        hh[k] = *reinterpret_cast<unsigned short*>(&h);
        ll[k] = *reinterpret_cast<unsigned short*>(&l);
    }
    *(uint4*)(ohi + (size_t)n * HID + 8 * t) = *(uint4*)hh;
    *(uint4*)(olo + (size_t)n * HID + 8 * t) = *(uint4*)ll;
}
// layer 4: 16 thr/node, 4 halfs each; + bias + log_softmax
__global__ __launch_bounds__(256) void agg40_lsm_kernel(
    const float* __restrict__ b4, float* __restrict__ out) {
    int n = blockIdx.x * 16 + (threadIdx.x >> 4);
    int t = threadIdx.x & 15;                // cols [4t, 4t+4)
    if (n >= NNODES) return;
    const uint2* hr = reinterpret_cast<const uint2*>(g_hs4h);
    int beg = g_rowptr[n], end = g_rowptr[n + 1];
    float a[4] = {0.f, 0.f, 0.f, 0.f};
    acc4(a, hr[(size_t)n * 16 + t]);
    int e = beg;
    for (; e + 2 <= end; e += 2) {
        uint2 u = hr[(size_t)g_srcs[e] * 16 + t];
        uint2 v = hr[(size_t)g_srcs[e + 1] * 16 + t];
        acc4(a, u); acc4(a, v);
    }
    if (e < end) acc4(a, hr[(size_t)g_srcs[e] * 16 + t]);
    float sc = g_is[n];
    int col0 = 4 * t;
    float v[4];
#pragma unroll
    for (int k = 0; k < 4; k++)
        v[k] = (col0 + k < NCLS) ? (sc * a[k] + b4[col0 + k]) : -1e30f;
    float m = fmaxf(fmaxf(v[0], v[1]), fmaxf(v[2], v[3]));
#pragma unroll
    for (int off = 8; off; off >>= 1) m = fmaxf(m, __shfl_xor_sync(0xffffffffu, m, off));
    float se = 0.f;
#pragma unroll
    for (int k = 0; k < 4; k++) se += (col0 + k < NCLS) ? __expf(v[k] - m) : 0.f;
#pragma unroll
    for (int off = 8; off; off >>= 1) se += __shfl_xor_sync(0xffffffffu, se, off);
    float lse = m + __logf(se);
    if (t < 10) {
        float4 o;
        o.x = v[0] - lse; o.y = v[1] - lse; o.z = v[2] - lse; o.w = v[3] - lse;
        *(float4*)(out + (size_t)n * NCLS + col0) = o;
    }
}

// ================= HMMA bf16x2-split GEMM, cp.async pipelined =================
// MODE 0: Ch[m,n] = (D * g_is[m]) fp16 ; MODE 1: relu(D + bias[n]) -> Chi/Clo bf16 hi/lo.
#define ASTR 72

template <int KT, int BN_T, int MODE>
__global__ __launch_bounds__(256) void mma_gemm_kernel(
    const __nv_bfloat16* __restrict__ Ahi, const __nv_bfloat16* __restrict__ Alo,
    const __nv_bfloat16* __restrict__ Bhi, const __nv_bfloat16* __restrict__ Blo,
    int NT,
    __half* __restrict__ Ch,
    __nv_bfloat16* __restrict__ Chi, __nv_bfloat16* __restrict__ Clo,
    const float* __restrict__ bias)
{
    extern __shared__ __nv_bfloat16 sm[];
    constexpr int NCH = KT / 64;
    constexpr int BSTR = KT + 8;
    constexpr int AHALF_B = 128 * ASTR * 2;
    constexpr int ASTG_B  = 2 * AHALF_B;
    constexpr int ABUF_B  = 2 * ASTG_B;
    constexpr int BHALF_B = BN_T * BSTR * 2;

    const int tid = threadIdx.x;
    const int lane = tid & 31;
    const int wid = tid >> 5;
    const int wm = wid & 3;
    const int wn = wid >> 2;
    constexpr int WN = BN_T / 2;
    constexpr int NTILES = WN / 8;

    const int row0 = blockIdx.x * 128;
    const int col0 = blockIdx.y * BN_T;

    const uint32_t uS = smem_u32(sm);
    const uint32_t uB = uS + ABUF_B;

    auto loadA = [&](int c) {
        int k0 = c * 64;
        uint32_t ab = uS + (c & 1) * ASTG_B;
#pragma unroll
        for (int it = 0; it < 4; it++) {
            int idx = tid + it * 256;
            int r = idx >> 3, q = idx & 7;
            int gr = row0 + r;
            int sz = (gr < NNODES) ? 16 : 0;
            uint32_t d = ab + (uint32_t)(r * ASTR + q * 8) * 2;
            cp_async16(d,           Ahi + (size_t)gr * KT + k0 + q * 8, sz);
            cp_async16(d + AHALF_B, Alo + (size_t)gr * KT + k0 + q * 8, sz);
        }
    };

    {
        constexpr int BUNITS = BN_T * KT / 8;
        for (int u = tid; u < BUNITS; u += 256) {
            int n = u / (KT / 8), q = u % (KT / 8);
            uint32_t d = uB + (uint32_t)(n * BSTR + q * 8) * 2;
            cp_async16(d,           Bhi + (size_t)(col0 + n) * KT + q * 8, 16);
            cp_async16(d + BHALF_B, Blo + (size_t)(col0 + n) * KT + q * 8, 16);
        }
        loadA(0);
        CP_COMMIT();
    }

    float acc[2][NTILES][4];
#pragma unroll
    for (int i = 0; i < 2; i++)
#pragma unroll
        for (int j = 0; j < NTILES; j++)
#pragma unroll
            for (int q = 0; q < 4; q++) acc[i][j][q] = 0.0f;

    const int a_r = (lane & 7) + ((lane >> 3) & 1) * 8;
    const int a_k = (lane >> 4) * 8;
    const int b_n = (lane & 7) + ((lane >> 4) & 1) * 8;
    const int b_k = ((lane >> 3) & 1) * 8;

#pragma unroll
    for (int c = 0; c < NCH; c++) {
        if (c + 1 < NCH) {
            loadA(c + 1);
            CP_COMMIT();
            asm volatile("cp.async.wait_group 1;");
        } else {
            asm volatile("cp.async.wait_group 0;");
        }
        __syncthreads();

        uint32_t abh = uS + (c & 1) * ASTG_B;
        uint32_t abl = abh + AHALF_B;
#pragma unroll
        for (int ks = 0; ks < 4; ks++) {
            uint32_t ah[2][4], al[2][4];
#pragma unroll
            for (int mt = 0; mt < 2; mt++) {
                uint32_t off = (uint32_t)(((wm * 32 + mt * 16 + a_r) * ASTR + ks * 16 + a_k) * 2);
                ldsm_x4(ah[mt][0], ah[mt][1], ah[mt][2], ah[mt][3], abh + off);
                ldsm_x4(al[mt][0], al[mt][1], al[mt][2], al[mt][3], abl + off);
            }
            uint32_t bh[NTILES][2], bl[NTILES][2];
#pragma unroll
            for (int nb = 0; nb < NTILES / 2; nb++) {
                uint32_t off = (uint32_t)(((wn * WN + nb * 16 + b_n) * BSTR + c * 64 + ks * 16 + b_k) * 2);
                uint32_t r0, r1, r2, r3;
                ldsm_x4(r0, r1, r2, r3, uB + off);
                bh[nb * 2][0] = r0; bh[nb * 2][1] = r1;
                bh[nb * 2 + 1][0] = r2; bh[nb * 2 + 1][1] = r3;
                ldsm_x4(r0, r1, r2, r3, uB + BHALF_B + off);
                bl[nb * 2][0] = r0; bl[nb * 2][1] = r1;
                bl[nb * 2 + 1][0] = r2; bl[nb * 2 + 1][1] = r3;
            }
#pragma unroll
            for (int mt = 0; mt < 2; mt++)
#pragma unroll
                for (int nt = 0; nt < NTILES; nt++) {
                    mma16816(acc[mt][nt][0], acc[mt][nt][1], acc[mt][nt][2], acc[mt][nt][3],
                             ah[mt][0], ah[mt][1], ah[mt][2], ah[mt][3], bh[nt][0], bh[nt][1]);
                    mma16816(acc[mt][nt][0], acc[mt][nt][1], acc[mt][nt][2], acc[mt][nt][3],
                             ah[mt][0], ah[mt][1], ah[mt][2], ah[mt][3], bl[nt][0], bl[nt][1]);
                    mma16816(acc[mt][nt][0], acc[mt][nt][1], acc[mt][nt][2], acc[mt][nt][3],
                             al[mt][0], al[mt][1], al[mt][2], al[mt][3], bh[nt][0], bh[nt][1]);
                }
        }
        __syncthreads();
    }

    // ---- epilogue ----
    const int rbase = row0 + wm * 32 + (lane >> 2);
    const int cbase = col0 + wn * WN + ((lane & 3) * 2);
#pragma unroll
    for (int mt = 0; mt < 2; mt++) {
#pragma unroll
        for (int half = 0; half < 2; half++) {
            int gr = rbase + mt * 16 + half * 8;
            if (gr < NNODES) {
                if (MODE == 0) {
                    float s = g_is[gr];
#pragma unroll
                    for (int nt = 0; nt < NTILES; nt++) {
                        __half2 p = __floats2half2_rn(acc[mt][nt][half * 2 + 0] * s,
                                                      acc[mt][nt][half * 2 + 1] * s);
                        *(__half2*)(Ch + (size_t)gr * NT + cbase + nt * 8) = p;
                    }
                } else {
#pragma unroll
                    for (int nt = 0; nt < NTILES; nt++) {
                        int c = cbase + nt * 8;
                        float v0 = fmaxf(acc[mt][nt][half * 2 + 0] + bias[c], 0.0f);
                        float v1 = fmaxf(acc[mt][nt][half * 2 + 1] + bias[c + 1], 0.0f);
                        __nv_bfloat16 h0 = __float2bfloat16(v0);
                        __nv_bfloat16 h1 = __float2bfloat16(v1);
                        __nv_bfloat162 hp; hp.x = h0; hp.y = h1;
                        __nv_bfloat162 lp;
                        lp.x = __float2bfloat16(v0 - __bfloat162float(h0));
                        lp.y = __float2bfloat16(v1 - __bfloat162float(h1));
                        *(__nv_bfloat162*)(Chi + (size_t)gr * NT + c) = hp;
                        *(__nv_bfloat162*)(Clo + (size_t)gr * NT + c) = lp;
                    }
                }
            }
        }
    }
}

// ================= launch =================
extern "C" void kernel_launch(void* const* d_in, const int* in_sizes, int n_in,
                              void* d_out, int out_size)
{
    const float* x  = (const float*)d_in[0];
    const int*   ei = (const int*)  d_in[1];
    const float* W1 = (const float*)d_in[2];
    const float* b1 = (const float*)d_in[3];
    const float* W2 = (const float*)d_in[4];
    const float* b2 = (const float*)d_in[5];
    const float* W3 = (const float*)d_in[6];
    const float* b3 = (const float*)d_in[7];
    const float* W4 = (const float*)d_in[8];
    const float* b4 = (const float*)d_in[9];
    float* out = (float*)d_out;

    const int* src = ei;
    const int* dst = ei + NEDGES;

    __nv_bfloat16 *thi, *tlo, *h0hi, *h0lo, *h1hi, *h1lo;
    __nv_bfloat16 *wt1hi, *wt1lo, *wt2hi, *wt2lo, *wt3hi, *wt3lo, *wt4hi, *wt4lo;
    __half *hsh, *hs4h;
    int *cntp, *fillp;
    cudaGetSymbolAddress((void**)&thi,  g_thi);   cudaGetSymbolAddress((void**)&tlo,  g_tlo);
    cudaGetSymbolAddress((void**)&h0hi, g_h0hi);  cudaGetSymbolAddress((void**)&h0lo, g_h0lo);
    cudaGetSymbolAddress((void**)&h1hi, g_h1hi);  cudaGetSymbolAddress((void**)&h1lo, g_h1lo);
    cudaGetSymbolAddress((void**)&wt1hi, g_wt1hi); cudaGetSymbolAddress((void**)&wt1lo, g_wt1lo);
    cudaGetSymbolAddress((void**)&wt2hi, g_wt2hi); cudaGetSymbolAddress((void**)&wt2lo, g_wt2lo);
    cudaGetSymbolAddress((void**)&wt3hi, g_wt3hi); cudaGetSymbolAddress((void**)&wt3lo, g_wt3lo);
    cudaGetSymbolAddress((void**)&wt4hi, g_wt4hi); cudaGetSymbolAddress((void**)&wt4lo, g_wt4lo);
    cudaGetSymbolAddress((void**)&hsh,  g_hsh);
    cudaGetSymbolAddress((void**)&hs4h, g_hs4h);
    cudaGetSymbolAddress((void**)&cntp, g_cnt);
    cudaGetSymbolAddress((void**)&fillp, g_fill);

    const int SMEM_L1 = 73728 + 2 * 128 * (128 + 8) * 2;  // 143360
    const int SMEM_L2 = 73728 + 2 * 128 * (256 + 8) * 2;  // 208896
    const int SMEM_L4 = 73728 + 2 * 64  * (256 + 8) * 2;  // 141312
    cudaFuncSetAttribute(mma_gemm_kernel<128, 128, 1>, cudaFuncAttributeMaxDynamicSharedMemorySize, SMEM_L1);
    cudaFuncSetAttribute(mma_gemm_kernel<256, 128, 0>, cudaFuncAttributeMaxDynamicSharedMemorySize, SMEM_L2);
    cudaFuncSetAttribute(mma_gemm_kernel<256, 64, 0>,  cudaFuncAttributeMaxDynamicSharedMemorySize, SMEM_L4);

    const int TB = 256;
    int edgeBlocks = (NEDGES + TB - 1) / TB;

    // ---- graph build ----
    cudaMemsetAsync(cntp, 0, NNODES * sizeof(int));
    cudaMemsetAsync(fillp, 0, NNODES * sizeof(int));
    degree_kernel<<<edgeBlocks, TB>>>(dst);
    scan_block_kernel<<<NB_SCAN, 1024>>>();
    scan_tops_kernel<<<1, 64>>>();
    scan_add_kernel<<<NB_SCAN, 1024>>>();
    fill_kernel<<<edgeBlocks, TB>>>(src, dst);

    // ---- weight + x prep ----
    wprep_kernel<<<(FIN * HID + TB - 1) / TB, TB>>>(W1, FIN, HID, HID, wt1hi, wt1lo);
    wprep_kernel<<<(HID * HID + TB - 1) / TB, TB>>>(W2, HID, HID, HID, wt2hi, wt2lo);
    wprep_kernel<<<(HID * HID + TB - 1) / TB, TB>>>(W3, HID, HID, HID, wt3hi, wt3lo);
    wprep_kernel<<<(HID * CPAD + TB - 1) / TB, TB>>>(W4, HID, NCLS, CPAD, wt4hi, wt4lo);
    xprep_kernel<<<(NNODES * FIN / 4 + TB - 1) / TB, TB>>>((const float4*)x);

    int mBlocks = (NNODES + 127) / 128;          // 391
    dim3 gHID(mBlocks, 2);
    dim3 gC(mBlocks, 1);
    int warpNodeBlocks = (NNODES + 7) / 8;       // 6250
    int a40Blocks = (NNODES + 15) / 16;          // 3125

    // layer 1: aggregate-first (fp16 gather), GEMM fused bias+relu+split
    agg_x_kernel<<<warpNodeBlocks, TB>>>();
    mma_gemm_kernel<128, 128, 1><<<gHID, 256, SMEM_L1>>>(
        thi, tlo, wt1hi, wt1lo, HID, nullptr, h0hi, h0lo, b1);
    // layer 2
    mma_gemm_kernel<256, 128, 0><<<gHID, 256, SMEM_L2>>>(
        h0hi, h0lo, wt2hi, wt2lo, HID, hsh, nullptr, nullptr, nullptr);
    agg_mid_kernel<<<warpNodeBlocks, TB>>>(hsh, b2, h1hi, h1lo);
    // layer 3
    mma_gemm_kernel<256, 128, 0><<<gHID, 256, SMEM_L2>>>(
        h1hi, h1lo, wt3hi, wt3lo, HID, hsh, nullptr, nullptr, nullptr);
    agg_mid_kernel<<<warpNodeBlocks, TB>>>(hsh, b3, h0hi, h0lo);
    // layer 4 + log_softmax
    mma_gemm_kernel<256, 64, 0><<<gC, 256, SMEM_L4>>>(
        h0hi, h0lo, wt4hi, wt4lo, CPAD, hs4h, nullptr, nullptr, nullptr);
    agg40_lsm_kernel<<<a40Blocks, TB>>>(b4, out);
}

// round 12
// speedup vs baseline: 2.5350x; 1.0078x over previous
#include <cuda_runtime.h>
#include <cuda_bf16.h>
#include <cuda_fp16.h>
#include <cstdint>
#include <cstddef>

#define NNODES 50000
#define NEDGES 1600000
#define FIN    128
#define HID    256
#define NCLS   40
#define CPAD   64
#define NB_SCAN 49   // ceil(50000/1024)

// ================= static device scratch =================
__device__ float g_is[NNODES];
__device__ int   g_cnt[NNODES];
__device__ int   g_fill[NNODES];
__device__ int   g_rowptr[NNODES + 1];
__device__ int   g_srcs[NEDGES];
__device__ int   g_bsum[NB_SCAN];
__device__ int   g_boff[NB_SCAN];

__device__ __half g_xs[(size_t)NNODES * FIN];     // is[n]*x[n] in fp16
__device__ __half g_hsh[(size_t)NNODES * HID];    // GEMM out (scaled) fp16 gather table
__device__ __half g_hs4h[(size_t)NNODES * CPAD];  // layer-4 GEMM out fp16

__device__ __nv_bfloat16 g_thi[(size_t)NNODES * FIN];
__device__ __nv_bfloat16 g_tlo[(size_t)NNODES * FIN];
__device__ __nv_bfloat16 g_h0hi[(size_t)NNODES * HID];
__device__ __nv_bfloat16 g_h0lo[(size_t)NNODES * HID];
__device__ __nv_bfloat16 g_h1hi[(size_t)NNODES * HID];
__device__ __nv_bfloat16 g_h1lo[(size_t)NNODES * HID];

// weights transposed+split: Wt[n][k] row-major [Npad][K]
__device__ __nv_bfloat16 g_wt1hi[HID * FIN],  g_wt1lo[HID * FIN];
__device__ __nv_bfloat16 g_wt2hi[HID * HID],  g_wt2lo[HID * HID];
__device__ __nv_bfloat16 g_wt3hi[HID * HID],  g_wt3lo[HID * HID];
__device__ __nv_bfloat16 g_wt4hi[CPAD * HID], g_wt4lo[CPAD * HID];

// ================= PTX helpers (base compute_103-legal only) =================
__device__ __forceinline__ uint32_t smem_u32(const void* p) {
    uint32_t a;
    asm("{ .reg .u64 t; cvta.to.shared.u64 t, %1; cvt.u32.u64 %0, t; }" : "=r"(a) : "l"(p));
    return a;
}
__device__ __forceinline__ void ldsm_x4(uint32_t& r0, uint32_t& r1, uint32_t& r2, uint32_t& r3,
                                        uint32_t addr) {
    asm volatile("ldmatrix.sync.aligned.m8n8.x4.shared.b16 {%0,%1,%2,%3}, [%4];"
                 : "=r"(r0), "=r"(r1), "=r"(r2), "=r"(r3) : "r"(addr));
}
__device__ __forceinline__ void mma16816(float& c0, float& c1, float& c2, float& c3,
                                         uint32_t a0, uint32_t a1, uint32_t a2, uint32_t a3,
                                         uint32_t b0, uint32_t b1) {
    asm volatile("mma.sync.aligned.m16n8k16.row.col.f32.bf16.bf16.f32 "
                 "{%0,%1,%2,%3}, {%4,%5,%6,%7}, {%8,%9}, {%0,%1,%2,%3};"
                 : "+f"(c0), "+f"(c1), "+f"(c2), "+f"(c3)
                 : "r"(a0), "r"(a1), "r"(a2), "r"(a3), "r"(b0), "r"(b1));
}
__device__ __forceinline__ void cp_async16(uint32_t dst, const void* src, int sz) {
    asm volatile("cp.async.cg.shared.global [%0], [%1], 16, %2;"
                 :: "r"(dst), "l"(src), "r"(sz));
}
#define CP_COMMIT() asm volatile("cp.async.commit_group;")

__device__ __forceinline__ void acc8(float* a, uint4 v) {
    __half2* h = reinterpret_cast<__half2*>(&v);
#pragma unroll
    for (int i = 0; i < 4; i++) {
        float2 f = __half22float2(h[i]);
        a[2 * i]     += f.x;
        a[2 * i + 1] += f.y;
    }
}
__device__ __forceinline__ void acc4(float* a, uint2 v) {
    __half2* h = reinterpret_cast<__half2*>(&v);
#pragma unroll
    for (int i = 0; i < 2; i++) {
        float2 f = __half22float2(h[i]);
        a[2 * i]     += f.x;
        a[2 * i + 1] += f.y;
    }
}

// ================= graph preprocessing =================
__global__ void degree_kernel(const int* __restrict__ dst) {
    int e = blockIdx.x * blockDim.x + threadIdx.x;
    if (e < NEDGES) atomicAdd(&g_cnt[dst[e]], 1);
}
__global__ __launch_bounds__(1024) void scan_block_kernel() {   // also computes g_is
    __shared__ int ws[32];
    int t = threadIdx.x, b = blockIdx.x;
    int i = b * 1024 + t;
    int v = (i < NNODES) ? g_cnt[i] : 0;
    if (i < NNODES) g_is[i] = rsqrtf((float)v + 1.0f);
    int lane = t & 31, w = t >> 5;
    int x = v;
#pragma unroll
    for (int off = 1; off < 32; off <<= 1) {
        int y = __shfl_up_sync(0xffffffffu, x, off);
        if (lane >= off) x += y;
    }
    if (lane == 31) ws[w] = x;
    __syncthreads();
    if (w == 0) {
        int s = ws[lane];
#pragma unroll
        for (int off = 1; off < 32; off <<= 1) {
            int y = __shfl_up_sync(0xffffffffu, s, off);
            if (lane >= off) s += y;
        }
        ws[lane] = s;
    }
    __syncthreads();
    int incl = x + (w ? ws[w - 1] : 0);
    if (i < NNODES) g_rowptr[i] = incl - v;
    if (t == 1023) g_bsum[b] = incl;
}
__global__ void scan_tops_kernel() {
    __shared__ int s[64];
    int t = threadIdx.x;
    int v = (t < NB_SCAN) ? g_bsum[t] : 0;
    s[t] = v;
    __syncthreads();
    for (int off = 1; off < 64; off <<= 1) {
        int y = (t >= off) ? s[t - off] : 0;
        __syncthreads();
        s[t] += y;
        __syncthreads();
    }
    if (t < NB_SCAN) g_boff[t] = s[t] - v;
    if (t == NB_SCAN - 1) g_rowptr[NNODES] = s[t];
}
__global__ __launch_bounds__(1024) void scan_add_kernel() {
    int i = blockIdx.x * 1024 + threadIdx.x;
    if (i < NNODES) g_rowptr[i] += g_boff[blockIdx.x];
}
__global__ void fill_kernel(const int* __restrict__ src, const int* __restrict__ dst) {
    int e = blockIdx.x * blockDim.x + threadIdx.x;
    if (e < NEDGES) {
        int d = dst[e];
        int p = atomicAdd(&g_fill[d], 1);
        g_srcs[g_rowptr[d] + p] = src[e];
    }
}
// all 4 weights transposed + split, one launch. piecewise index map.
#define W1E (FIN * HID)     // 32768
#define W2E (HID * HID)     // 65536
#define W3E (HID * HID)     // 65536
#define W4E (HID * CPAD)    // 16384
__global__ void wprep_all_kernel(const float* __restrict__ W1, const float* __restrict__ W2,
                                 const float* __restrict__ W3, const float* __restrict__ W4) {
    int i = blockIdx.x * blockDim.x + threadIdx.x;
    const float* W; __nv_bfloat16 *dhi, *dlo;
    int K, Nw, Npad, j;
    if (i < W1E) { W = W1; dhi = g_wt1hi; dlo = g_wt1lo; K = FIN; Nw = HID; Npad = HID; j = i; }
    else if (i < W1E + W2E) { W = W2; dhi = g_wt2hi; dlo = g_wt2lo; K = HID; Nw = HID; Npad = HID; j = i - W1E; }
    else if (i < W1E + W2E + W3E) { W = W3; dhi = g_wt3hi; dlo = g_wt3lo; K = HID; Nw = HID; Npad = HID; j = i - W1E - W2E; }
    else if (i < W1E + W2E + W3E + W4E) { W = W4; dhi = g_wt4hi; dlo = g_wt4lo; K = HID; Nw = NCLS; Npad = CPAD; j = i - W1E - W2E - W3E; }
    else return;
    int n = j / K, k = j % K;
    float v = (n < Nw) ? W[k * Nw + n] : 0.0f;
    __nv_bfloat16 h = __float2bfloat16(v);
    dhi[j] = h;
    dlo[j] = __float2bfloat16(v - __bfloat162float(h));
}
// xs[n][f] = is[n] * x[n][f]  (fp16)
__global__ void xprep_kernel(const float4* __restrict__ x) {
    int i = blockIdx.x * blockDim.x + threadIdx.x;   // one float4 (4 feats)
    if (i < NNODES * FIN / 4) {
        int n = i >> 5;                              // 32 float4 per node
        float isn = g_is[n];
        float4 v = x[i];
        __half2* o = reinterpret_cast<__half2*>(g_xs) + 2 * i;
        o[0] = __floats2half2_rn(isn * v.x, isn * v.y);
        o[1] = __floats2half2_rn(isn * v.z, isn * v.w);
    }
}

// ================= aggregation kernels (fp16 gather, fp32 accum, MLP-4 unroll) ==========
// layer-1: warp per node; t[n] = is[n]*(sum_src xs[src] + xs[n]) -> bf16 hi/lo
__global__ __launch_bounds__(256) void agg_x_kernel() {
    int n = blockIdx.x * 8 + (threadIdx.x >> 5);
    int t = threadIdx.x & 31;                // 4 feats per thread
    if (n >= NNODES) return;
    const uint2* xr = reinterpret_cast<const uint2*>(g_xs);
    int beg = g_rowptr[n], end = g_rowptr[n + 1];
    float a[4] = {0.f, 0.f, 0.f, 0.f};
    acc4(a, xr[(size_t)n * 32 + t]);         // self (xs already is-scaled)
    int e = beg;
    for (; e + 4 <= end; e += 4) {
        int s0 = g_srcs[e], s1 = g_srcs[e + 1], s2 = g_srcs[e + 2], s3 = g_srcs[e + 3];
        uint2 u0 = xr[(size_t)s0 * 32 + t];
        uint2 u1 = xr[(size_t)s1 * 32 + t];
        uint2 u2 = xr[(size_t)s2 * 32 + t];
        uint2 u3 = xr[(size_t)s3 * 32 + t];
        acc4(a, u0); acc4(a, u1); acc4(a, u2); acc4(a, u3);
    }
    for (; e < end; e++) acc4(a, xr[(size_t)g_srcs[e] * 32 + t]);
    float isn = g_is[n];
    unsigned short hh[4], ll[4];
#pragma unroll
    for (int k = 0; k < 4; k++) {
        float v = isn * a[k];
        __nv_bfloat16 h = __float2bfloat16(v);
        __nv_bfloat16 l = __float2bfloat16(v - __bfloat162float(h));
        hh[k] = *reinterpret_cast<unsigned short*>(&h);
        ll[k] = *reinterpret_cast<unsigned short*>(&l);
    }
    *(uint2*)(g_thi + (size_t)n * FIN + 4 * t) = *(uint2*)hh;
    *(uint2*)(g_tlo + (size_t)n * FIN + 4 * t) = *(uint2*)ll;
}
// mid layers: warp per node, 8 feats per thread (uint4 = 8 halfs)
__global__ __launch_bounds__(256) void agg_mid_kernel(
    const __half* __restrict__ hs, const float* __restrict__ bias,
    __nv_bfloat16* __restrict__ ohi, __nv_bfloat16* __restrict__ olo) {
    int n = blockIdx.x * 8 + (threadIdx.x >> 5);
    int t = threadIdx.x & 31;                // feats [8t, 8t+8)
    if (n >= NNODES) return;
    const uint4* hr = reinterpret_cast<const uint4*>(hs);
    int beg = g_rowptr[n], end = g_rowptr[n + 1];
    float a[8] = {0.f, 0.f, 0.f, 0.f, 0.f, 0.f, 0.f, 0.f};
    acc8(a, hr[(size_t)n * 32 + t]);         // self
    int e = beg;
    for (; e + 4 <= end; e += 4) {
        int s0 = g_srcs[e], s1 = g_srcs[e + 1], s2 = g_srcs[e + 2], s3 = g_srcs[e + 3];
        uint4 u0 = hr[(size_t)s0 * 32 + t];
        uint4 u1 = hr[(size_t)s1 * 32 + t];
        uint4 u2 = hr[(size_t)s2 * 32 + t];
        uint4 u3 = hr[(size_t)s3 * 32 + t];
        acc8(a, u0); acc8(a, u1); acc8(a, u2); acc8(a, u3);
    }
    for (; e < end; e++) acc8(a, hr[(size_t)g_srcs[e] * 32 + t]);
    float isn = g_is[n];
    unsigned short hh[8], ll[8];
#pragma unroll
    for (int k = 0; k < 8; k++) {
        float v = fmaxf(isn * a[k] + bias[8 * t + k], 0.0f);
        __nv_bfloat16 h = __float2bfloat16(v);
        __nv_bfloat16 l = __float2bfloat16(v - __bfloat162float(h));
        hh[k] = *reinterpret_cast<unsigned short*>(&h);
        ll[k] = *reinterpret_cast<unsigned short*>(&l);
    }
    *(uint4*)(ohi + (size_t)n * HID + 8 * t) = *(uint4*)hh;
    *(uint4*)(olo + (size_t)n * HID + 8 * t) = *(uint4*)ll;
}
// layer 4: 16 thr/node, 4 halfs each; + bias + log_softmax
__global__ __launch_bounds__(256) void agg40_lsm_kernel(
    const float* __restrict__ b4, float* __restrict__ out) {
    int n = blockIdx.x * 16 + (threadIdx.x >> 4);
    int t = threadIdx.x & 15;                // cols [4t, 4t+4)
    if (n >= NNODES) return;
    const uint2* hr = reinterpret_cast<const uint2*>(g_hs4h);
    int beg = g_rowptr[n], end = g_rowptr[n + 1];
    float a[4] = {0.f, 0.f, 0.f, 0.f};
    acc4(a, hr[(size_t)n * 16 + t]);
    int e = beg;
    for (; e + 4 <= end; e += 4) {
        int s0 = g_srcs[e], s1 = g_srcs[e + 1], s2 = g_srcs[e + 2], s3 = g_srcs[e + 3];
        uint2 u0 = hr[(size_t)s0 * 16 + t];
        uint2 u1 = hr[(size_t)s1 * 16 + t];
        uint2 u2 = hr[(size_t)s2 * 16 + t];
        uint2 u3 = hr[(size_t)s3 * 16 + t];
        acc4(a, u0); acc4(a, u1); acc4(a, u2); acc4(a, u3);
    }
    for (; e < end; e++) acc4(a, hr[(size_t)g_srcs[e] * 16 + t]);
    float sc = g_is[n];
    int col0 = 4 * t;
    float v[4];
#pragma unroll
    for (int k = 0; k < 4; k++)
        v[k] = (col0 + k < NCLS) ? (sc * a[k] + b4[col0 + k]) : -1e30f;
    float m = fmaxf(fmaxf(v[0], v[1]), fmaxf(v[2], v[3]));
#pragma unroll
    for (int off = 8; off; off >>= 1) m = fmaxf(m, __shfl_xor_sync(0xffffffffu, m, off));
    float se = 0.f;
#pragma unroll
    for (int k = 0; k < 4; k++) se += (col0 + k < NCLS) ? __expf(v[k] - m) : 0.f;
#pragma unroll
    for (int off = 8; off; off >>= 1) se += __shfl_xor_sync(0xffffffffu, se, off);
    float lse = m + __logf(se);
    if (t < 10) {
        float4 o;
        o.x = v[0] - lse; o.y = v[1] - lse; o.z = v[2] - lse; o.w = v[3] - lse;
        *(float4*)(out + (size_t)n * NCLS + col0) = o;
    }
}

// ================= HMMA bf16x2-split GEMM, cp.async pipelined =================
// MODE 0: Ch[m,n] = (D * g_is[m]) fp16 ; MODE 1: relu(D + bias[n]) -> Chi/Clo bf16 hi/lo.
#define ASTR 72

template <int KT, int BN_T, int MODE>
__global__ __launch_bounds__(256) void mma_gemm_kernel(
    const __nv_bfloat16* __restrict__ Ahi, const __nv_bfloat16* __restrict__ Alo,
    const __nv_bfloat16* __restrict__ Bhi, const __nv_bfloat16* __restrict__ Blo,
    int NT,
    __half* __restrict__ Ch,
    __nv_bfloat16* __restrict__ Chi, __nv_bfloat16* __restrict__ Clo,
    const float* __restrict__ bias)
{
    extern __shared__ __nv_bfloat16 sm[];
    constexpr int NCH = KT / 64;
    constexpr int BSTR = KT + 8;
    constexpr int AHALF_B = 128 * ASTR * 2;
    constexpr int ASTG_B  = 2 * AHALF_B;
    constexpr int ABUF_B  = 2 * ASTG_B;
    constexpr int BHALF_B = BN_T * BSTR * 2;

    const int tid = threadIdx.x;
    const int lane = tid & 31;
    const int wid = tid >> 5;
    const int wm = wid & 3;
    const int wn = wid >> 2;
    constexpr int WN = BN_T / 2;
    constexpr int NTILES = WN / 8;

    const int row0 = blockIdx.x * 128;
    const int col0 = blockIdx.y * BN_T;

    const uint32_t uS = smem_u32(sm);
    const uint32_t uB = uS + ABUF_B;

    auto loadA = [&](int c) {
        int k0 = c * 64;
        uint32_t ab = uS + (c & 1) * ASTG_B;
#pragma unroll
        for (int it = 0; it < 4; it++) {
            int idx = tid + it * 256;
            int r = idx >> 3, q = idx & 7;
            int gr = row0 + r;
            int sz = (gr < NNODES) ? 16 : 0;
            uint32_t d = ab + (uint32_t)(r * ASTR + q * 8) * 2;
            cp_async16(d,           Ahi + (size_t)gr * KT + k0 + q * 8, sz);
            cp_async16(d + AHALF_B, Alo + (size_t)gr * KT + k0 + q * 8, sz);
        }
    };

    {
        constexpr int BUNITS = BN_T * KT / 8;
        for (int u = tid; u < BUNITS; u += 256) {
            int n = u / (KT / 8), q = u % (KT / 8);
            uint32_t d = uB + (uint32_t)(n * BSTR + q * 8) * 2;
            cp_async16(d,           Bhi + (size_t)(col0 + n) * KT + q * 8, 16);
            cp_async16(d + BHALF_B, Blo + (size_t)(col0 + n) * KT + q * 8, 16);
        }
        loadA(0);
        CP_COMMIT();
    }

    float acc[2][NTILES][4];
#pragma unroll
    for (int i = 0; i < 2; i++)
#pragma unroll
        for (int j = 0; j < NTILES; j++)
#pragma unroll
            for (int q = 0; q < 4; q++) acc[i][j][q] = 0.0f;

    const int a_r = (lane & 7) + ((lane >> 3) & 1) * 8;
    const int a_k = (lane >> 4) * 8;
    const int b_n = (lane & 7) + ((lane >> 4) & 1) * 8;
    const int b_k = ((lane >> 3) & 1) * 8;

#pragma unroll
    for (int c = 0; c < NCH; c++) {
        if (c + 1 < NCH) {
            loadA(c + 1);
            CP_COMMIT();
            asm volatile("cp.async.wait_group 1;");
        } else {
            asm volatile("cp.async.wait_group 0;");
        }
        __syncthreads();

        uint32_t abh = uS + (c & 1) * ASTG_B;
        uint32_t abl = abh + AHALF_B;
#pragma unroll
        for (int ks = 0; ks < 4; ks++) {
            uint32_t ah[2][4], al[2][4];
#pragma unroll
            for (int mt = 0; mt < 2; mt++) {
                uint32_t off = (uint32_t)(((wm * 32 + mt * 16 + a_r) * ASTR + ks * 16 + a_k) * 2);
                ldsm_x4(ah[mt][0], ah[mt][1], ah[mt][2], ah[mt][3], abh + off);
                ldsm_x4(al[mt][0], al[mt][1], al[mt][2], al[mt][3], abl + off);
            }
            uint32_t bh[NTILES][2], bl[NTILES][2];
#pragma unroll
            for (int nb = 0; nb < NTILES / 2; nb++) {
                uint32_t off = (uint32_t)(((wn * WN + nb * 16 + b_n) * BSTR + c * 64 + ks * 16 + b_k) * 2);
                uint32_t r0, r1, r2, r3;
                ldsm_x4(r0, r1, r2, r3, uB + off);
                bh[nb * 2][0] = r0; bh[nb * 2][1] = r1;
                bh[nb * 2 + 1][0] = r2; bh[nb * 2 + 1][1] = r3;
                ldsm_x4(r0, r1, r2, r3, uB + BHALF_B + off);
                bl[nb * 2][0] = r0; bl[nb * 2][1] = r1;
                bl[nb * 2 + 1][0] = r2; bl[nb * 2 + 1][1] = r3;
            }
#pragma unroll
            for (int mt = 0; mt < 2; mt++)
#pragma unroll
                for (int nt = 0; nt < NTILES; nt++) {
                    mma16816(acc[mt][nt][0], acc[mt][nt][1], acc[mt][nt][2], acc[mt][nt][3],
                             ah[mt][0], ah[mt][1], ah[mt][2], ah[mt][3], bh[nt][0], bh[nt][1]);
                    mma16816(acc[mt][nt][0], acc[mt][nt][1], acc[mt][nt][2], acc[mt][nt][3],
                             ah[mt][0], ah[mt][1], ah[mt][2], ah[mt][3], bl[nt][0], bl[nt][1]);
                    mma16816(acc[mt][nt][0], acc[mt][nt][1], acc[mt][nt][2], acc[mt][nt][3],
                             al[mt][0], al[mt][1], al[mt][2], al[mt][3], bh[nt][0], bh[nt][1]);
                }
        }
        __syncthreads();
    }

    // ---- epilogue ----
    const int rbase = row0 + wm * 32 + (lane >> 2);
    const int cbase = col0 + wn * WN + ((lane & 3) * 2);
#pragma unroll
    for (int mt = 0; mt < 2; mt++) {
#pragma unroll
        for (int half = 0; half < 2; half++) {
            int gr = rbase + mt * 16 + half * 8;
            if (gr < NNODES) {
                if (MODE == 0) {
                    float s = g_is[gr];
#pragma unroll
                    for (int nt = 0; nt < NTILES; nt++) {
                        __half2 p = __floats2half2_rn(acc[mt][nt][half * 2 + 0] * s,
                                                      acc[mt][nt][half * 2 + 1] * s);
                        *(__half2*)(Ch + (size_t)gr * NT + cbase + nt * 8) = p;
                    }
                } else {
#pragma unroll
                    for (int nt = 0; nt < NTILES; nt++) {
                        int c = cbase + nt * 8;
                        float v0 = fmaxf(acc[mt][nt][half * 2 + 0] + bias[c], 0.0f);
                        float v1 = fmaxf(acc[mt][nt][half * 2 + 1] + bias[c + 1], 0.0f);
                        __nv_bfloat16 h0 = __float2bfloat16(v0);
                        __nv_bfloat16 h1 = __float2bfloat16(v1);
                        __nv_bfloat162 hp; hp.x = h0; hp.y = h1;
                        __nv_bfloat162 lp;
                        lp.x = __float2bfloat16(v0 - __bfloat162float(h0));
                        lp.y = __float2bfloat16(v1 - __bfloat162float(h1));
                        *(__nv_bfloat162*)(Chi + (size_t)gr * NT + c) = hp;
                        *(__nv_bfloat162*)(Clo + (size_t)gr * NT + c) = lp;
                    }
                }
            }
        }
    }
}

// ================= launch =================
extern "C" void kernel_launch(void* const* d_in, const int* in_sizes, int n_in,
                              void* d_out, int out_size)
{
    const float* x  = (const float*)d_in[0];
    const int*   ei = (const int*)  d_in[1];
    const float* W1 = (const float*)d_in[2];
    const float* b1 = (const float*)d_in[3];
    const float* W2 = (const float*)d_in[4];
    const float* b2 = (const float*)d_in[5];
    const float* W3 = (const float*)d_in[6];
    const float* b3 = (const float*)d_in[7];
    const float* W4 = (const float*)d_in[8];
    const float* b4 = (const float*)d_in[9];
    float* out = (float*)d_out;

    const int* src = ei;
    const int* dst = ei + NEDGES;

    __nv_bfloat16 *thi, *tlo, *h0hi, *h0lo, *h1hi, *h1lo;
    __nv_bfloat16 *wt1hi, *wt1lo, *wt2hi, *wt2lo, *wt3hi, *wt3lo, *wt4hi, *wt4lo;
    __half *hsh, *hs4h;
    int *cntp, *fillp;
    cudaGetSymbolAddress((void**)&thi,  g_thi);   cudaGetSymbolAddress((void**)&tlo,  g_tlo);
    cudaGetSymbolAddress((void**)&h0hi, g_h0hi);  cudaGetSymbolAddress((void**)&h0lo, g_h0lo);
    cudaGetSymbolAddress((void**)&h1hi, g_h1hi);  cudaGetSymbolAddress((void**)&h1lo, g_h1lo);
    cudaGetSymbolAddress((void**)&wt1hi, g_wt1hi); cudaGetSymbolAddress((void**)&wt1lo, g_wt1lo);
    cudaGetSymbolAddress((void**)&wt2hi, g_wt2hi); cudaGetSymbolAddress((void**)&wt2lo, g_wt2lo);
    cudaGetSymbolAddress((void**)&wt3hi, g_wt3hi); cudaGetSymbolAddress((void**)&wt3lo, g_wt3lo);
    cudaGetSymbolAddress((void**)&wt4hi, g_wt4hi); cudaGetSymbolAddress((void**)&wt4lo, g_wt4lo);
    cudaGetSymbolAddress((void**)&hsh,  g_hsh);
    cudaGetSymbolAddress((void**)&hs4h, g_hs4h);
    cudaGetSymbolAddress((void**)&cntp, g_cnt);
    cudaGetSymbolAddress((void**)&fillp, g_fill);

    const int SMEM_L1 = 73728 + 2 * 128 * (128 + 8) * 2;  // 143360
    const int SMEM_L2 = 73728 + 2 * 128 * (256 + 8) * 2;  // 208896
    const int SMEM_L4 = 73728 + 2 * 64  * (256 + 8) * 2;  // 141312
    cudaFuncSetAttribute(mma_gemm_kernel<128, 128, 1>, cudaFuncAttributeMaxDynamicSharedMemorySize, SMEM_L1);
    cudaFuncSetAttribute(mma_gemm_kernel<256, 128, 0>, cudaFuncAttributeMaxDynamicSharedMemorySize, SMEM_L2);
    cudaFuncSetAttribute(mma_gemm_kernel<256, 64, 0>,  cudaFuncAttributeMaxDynamicSharedMemorySize, SMEM_L4);

    const int TB = 256;
    int edgeBlocks = (NEDGES + TB - 1) / TB;

    // ---- graph build ----
    cudaMemsetAsync(cntp, 0, NNODES * sizeof(int));
    cudaMemsetAsync(fillp, 0, NNODES * sizeof(int));
    degree_kernel<<<edgeBlocks, TB>>>(dst);
    scan_block_kernel<<<NB_SCAN, 1024>>>();
    scan_tops_kernel<<<1, 64>>>();
    scan_add_kernel<<<NB_SCAN, 1024>>>();
    fill_kernel<<<edgeBlocks, TB>>>(src, dst);

    // ---- weight + x prep (merged) ----
    const int WALL = W1E + W2E + W3E + W4E;
    wprep_all_kernel<<<(WALL + TB - 1) / TB, TB>>>(W1, W2, W3, W4);
    xprep_kernel<<<(NNODES * FIN / 4 + TB - 1) / TB, TB>>>((const float4*)x);

    int mBlocks = (NNODES + 127) / 128;          // 391
    dim3 gHID(mBlocks, 2);
    dim3 gC(mBlocks, 1);
    int warpNodeBlocks = (NNODES + 7) / 8;       // 6250
    int a40Blocks = (NNODES + 15) / 16;          // 3125

    // layer 1: aggregate-first (fp16 gather), GEMM fused bias+relu+split
    agg_x_kernel<<<warpNodeBlocks, TB>>>();
    mma_gemm_kernel<128, 128, 1><<<gHID, 256, SMEM_L1>>>(
        thi, tlo, wt1hi, wt1lo, HID, nullptr, h0hi, h0lo, b1);
    // layer 2
    mma_gemm_kernel<256, 128, 0><<<gHID, 256, SMEM_L2>>>(
        h0hi, h0lo, wt2hi, wt2lo, HID, hsh, nullptr, nullptr, nullptr);
    agg_mid_kernel<<<warpNodeBlocks, TB>>>(hsh, b2, h1hi, h1lo);
    // layer 3
    mma_gemm_kernel<256, 128, 0><<<gHID, 256, SMEM_L2>>>(
        h1hi, h1lo, wt3hi, wt3lo, HID, hsh, nullptr, nullptr, nullptr);
    agg_mid_kernel<<<warpNodeBlocks, TB>>>(hsh, b3, h0hi, h0lo);
    // layer 4 + log_softmax
    mma_gemm_kernel<256, 64, 0><<<gC, 256, SMEM_L4>>>(
        h0hi, h0lo, wt4hi, wt4lo, CPAD, hs4h, nullptr, nullptr, nullptr);
    agg40_lsm_kernel<<<a40Blocks, TB>>>(b4, out);
}

// round 13
// speedup vs baseline: 3.5928x; 1.4173x over previous
#include <cuda_runtime.h>
#include <cuda_bf16.h>
#include <cuda_fp16.h>
#include <cstdint>
#include <cstddef>

#define NNODES 50000
#define NEDGES 1600000
#define FIN    128
#define HID    256
#define NCLS   40
#define CPAD   64
#define NB_SCAN 49   // ceil(50000/1024)

// ================= static device scratch =================
__device__ float g_is[NNODES];
__device__ int   g_cnt[NNODES];
__device__ int   g_fill[NNODES];
__device__ int   g_rowptr[NNODES + 1];
__device__ int   g_srcs[NEDGES];
__device__ int   g_bsum[NB_SCAN];
__device__ int   g_boff[NB_SCAN];

__device__ __half g_xs[(size_t)NNODES * FIN];     // is[n]*x[n] in fp16 (gather table)
__device__ __half g_hsh[(size_t)NNODES * HID];    // GEMM out (scaled) fp16 gather table
__device__ __half g_hs4h[(size_t)NNODES * CPAD];  // layer-4 GEMM out fp16

__device__ __nv_bfloat16 g_t[(size_t)NNODES * FIN];    // layer-1 GEMM input (bf16 single)
__device__ __nv_bfloat16 g_h0[(size_t)NNODES * HID];   // activations bf16 single
__device__ __nv_bfloat16 g_h1[(size_t)NNODES * HID];

// weights transposed (bf16 single): Wt[n][k] row-major [Npad][K]
__device__ __nv_bfloat16 g_wt1[HID * FIN];
__device__ __nv_bfloat16 g_wt2[HID * HID];
__device__ __nv_bfloat16 g_wt3[HID * HID];
__device__ __nv_bfloat16 g_wt4[CPAD * HID];

// ================= PTX helpers (base compute_103-legal only) =================
__device__ __forceinline__ uint32_t smem_u32(const void* p) {
    uint32_t a;
    asm("{ .reg .u64 t; cvta.to.shared.u64 t, %1; cvt.u32.u64 %0, t; }" : "=r"(a) : "l"(p));
    return a;
}
__device__ __forceinline__ void ldsm_x4(uint32_t& r0, uint32_t& r1, uint32_t& r2, uint32_t& r3,
                                        uint32_t addr) {
    asm volatile("ldmatrix.sync.aligned.m8n8.x4.shared.b16 {%0,%1,%2,%3}, [%4];"
                 : "=r"(r0), "=r"(r1), "=r"(r2), "=r"(r3) : "r"(addr));
}
__device__ __forceinline__ void mma16816(float& c0, float& c1, float& c2, float& c3,
                                         uint32_t a0, uint32_t a1, uint32_t a2, uint32_t a3,
                                         uint32_t b0, uint32_t b1) {
    asm volatile("mma.sync.aligned.m16n8k16.row.col.f32.bf16.bf16.f32 "
                 "{%0,%1,%2,%3}, {%4,%5,%6,%7}, {%8,%9}, {%0,%1,%2,%3};"
                 : "+f"(c0), "+f"(c1), "+f"(c2), "+f"(c3)
                 : "r"(a0), "r"(a1), "r"(a2), "r"(a3), "r"(b0), "r"(b1));
}
__device__ __forceinline__ void cp_async16(uint32_t dst, const void* src, int sz) {
    asm volatile("cp.async.cg.shared.global [%0], [%1], 16, %2;"
                 :: "r"(dst), "l"(src), "r"(sz));
}
#define CP_COMMIT() asm volatile("cp.async.commit_group;")

__device__ __forceinline__ void acc8(float* a, uint4 v) {
    __half2* h = reinterpret_cast<__half2*>(&v);
#pragma unroll
    for (int i = 0; i < 4; i++) {
        float2 f = __half22float2(h[i]);
        a[2 * i]     += f.x;
        a[2 * i + 1] += f.y;
    }
}
__device__ __forceinline__ void acc4(float* a, uint2 v) {
    __half2* h = reinterpret_cast<__half2*>(&v);
#pragma unroll
    for (int i = 0; i < 2; i++) {
        float2 f = __half22float2(h[i]);
        a[2 * i]     += f.x;
        a[2 * i + 1] += f.y;
    }
}

// ================= graph preprocessing =================
__global__ void degree_kernel(const int* __restrict__ dst) {
    int e = blockIdx.x * blockDim.x + threadIdx.x;
    if (e < NEDGES) atomicAdd(&g_cnt[dst[e]], 1);
}
__global__ __launch_bounds__(1024) void scan_block_kernel() {   // also computes g_is
    __shared__ int ws[32];
    int t = threadIdx.x, b = blockIdx.x;
    int i = b * 1024 + t;
    int v = (i < NNODES) ? g_cnt[i] : 0;
    if (i < NNODES) g_is[i] = rsqrtf((float)v + 1.0f);
    int lane = t & 31, w = t >> 5;
    int x = v;
#pragma unroll
    for (int off = 1; off < 32; off <<= 1) {
        int y = __shfl_up_sync(0xffffffffu, x, off);
        if (lane >= off) x += y;
    }
    if (lane == 31) ws[w] = x;
    __syncthreads();
    if (w == 0) {
        int s = ws[lane];
#pragma unroll
        for (int off = 1; off < 32; off <<= 1) {
            int y = __shfl_up_sync(0xffffffffu, s, off);
            if (lane >= off) s += y;
        }
        ws[lane] = s;
    }
    __syncthreads();
    int incl = x + (w ? ws[w - 1] : 0);
    if (i < NNODES) g_rowptr[i] = incl - v;
    if (t == 1023) g_bsum[b] = incl;
}
__global__ void scan_tops_kernel() {
    __shared__ int s[64];
    int t = threadIdx.x;
    int v = (t < NB_SCAN) ? g_bsum[t] : 0;
    s[t] = v;
    __syncthreads();
    for (int off = 1; off < 64; off <<= 1) {
        int y = (t >= off) ? s[t - off] : 0;
        __syncthreads();
        s[t] += y;
        __syncthreads();
    }
    if (t < NB_SCAN) g_boff[t] = s[t] - v;
    if (t == NB_SCAN - 1) g_rowptr[NNODES] = s[t];
}
__global__ __launch_bounds__(1024) void scan_add_kernel() {
    int i = blockIdx.x * 1024 + threadIdx.x;
    if (i < NNODES) g_rowptr[i] += g_boff[blockIdx.x];
}
__global__ void fill_kernel(const int* __restrict__ src, const int* __restrict__ dst) {
    int e = blockIdx.x * blockDim.x + threadIdx.x;
    if (e < NEDGES) {
        int d = dst[e];
        int p = atomicAdd(&g_fill[d], 1);
        g_srcs[g_rowptr[d] + p] = src[e];
    }
}
// all 4 weights transposed -> bf16, one launch. piecewise index map.
#define W1E (FIN * HID)     // 32768
#define W2E (HID * HID)     // 65536
#define W3E (HID * HID)     // 65536
#define W4E (HID * CPAD)    // 16384
__global__ void wprep_all_kernel(const float* __restrict__ W1, const float* __restrict__ W2,
                                 const float* __restrict__ W3, const float* __restrict__ W4) {
    int i = blockIdx.x * blockDim.x + threadIdx.x;
    const float* W; __nv_bfloat16* dw;
    int K, Nw, j;
    if (i < W1E) { W = W1; dw = g_wt1; K = FIN; Nw = HID; j = i; }
    else if (i < W1E + W2E) { W = W2; dw = g_wt2; K = HID; Nw = HID; j = i - W1E; }
    else if (i < W1E + W2E + W3E) { W = W3; dw = g_wt3; K = HID; Nw = HID; j = i - W1E - W2E; }
    else if (i < W1E + W2E + W3E + W4E) { W = W4; dw = g_wt4; K = HID; Nw = NCLS; j = i - W1E - W2E - W3E; }
    else return;
    int n = j / K, k = j % K;
    float v = (n < Nw) ? W[k * Nw + n] : 0.0f;
    dw[j] = __float2bfloat16(v);
}
// xs[n][f] = is[n] * x[n][f]  (fp16)
__global__ void xprep_kernel(const float4* __restrict__ x) {
    int i = blockIdx.x * blockDim.x + threadIdx.x;   // one float4 (4 feats)
    if (i < NNODES * FIN / 4) {
        int n = i >> 5;                              // 32 float4 per node
        float isn = g_is[n];
        float4 v = x[i];
        __half2* o = reinterpret_cast<__half2*>(g_xs) + 2 * i;
        o[0] = __floats2half2_rn(isn * v.x, isn * v.y);
        o[1] = __floats2half2_rn(isn * v.z, isn * v.w);
    }
}

// ================= aggregation kernels (fp16 gather, fp32 accum) =================
// layer-1: warp per node; t[n] = is[n]*(sum_src xs[src] + xs[n]) -> bf16 single
__global__ __launch_bounds__(256) void agg_x_kernel() {
    int n = blockIdx.x * 8 + (threadIdx.x >> 5);
    int t = threadIdx.x & 31;                // 4 feats per thread
    if (n >= NNODES) return;
    const uint2* xr = reinterpret_cast<const uint2*>(g_xs);
    int beg = g_rowptr[n], end = g_rowptr[n + 1];
    float a[4] = {0.f, 0.f, 0.f, 0.f};
    acc4(a, xr[(size_t)n * 32 + t]);         // self (xs already is-scaled)
    int e = beg;
    for (; e + 4 <= end; e += 4) {
        int s0 = g_srcs[e], s1 = g_srcs[e + 1], s2 = g_srcs[e + 2], s3 = g_srcs[e + 3];
        uint2 u0 = xr[(size_t)s0 * 32 + t];
        uint2 u1 = xr[(size_t)s1 * 32 + t];
        uint2 u2 = xr[(size_t)s2 * 32 + t];
        uint2 u3 = xr[(size_t)s3 * 32 + t];
        acc4(a, u0); acc4(a, u1); acc4(a, u2); acc4(a, u3);
    }
    for (; e < end; e++) acc4(a, xr[(size_t)g_srcs[e] * 32 + t]);
    float isn = g_is[n];
    unsigned short hh[4];
#pragma unroll
    for (int k = 0; k < 4; k++) {
        __nv_bfloat16 h = __float2bfloat16(isn * a[k]);
        hh[k] = *reinterpret_cast<unsigned short*>(&h);
    }
    *(uint2*)(g_t + (size_t)n * FIN + 4 * t) = *(uint2*)hh;
}
// mid layers: warp per node, 8 feats per thread; out = relu(is*sum + b) -> bf16 single
__global__ __launch_bounds__(256) void agg_mid_kernel(
    const __half* __restrict__ hs, const float* __restrict__ bias,
    __nv_bfloat16* __restrict__ oh) {
    int n = blockIdx.x * 8 + (threadIdx.x >> 5);
    int t = threadIdx.x & 31;                // feats [8t, 8t+8)
    if (n >= NNODES) return;
    const uint4* hr = reinterpret_cast<const uint4*>(hs);
    int beg = g_rowptr[n], end = g_rowptr[n + 1];
    float a[8] = {0.f, 0.f, 0.f, 0.f, 0.f, 0.f, 0.f, 0.f};
    acc8(a, hr[(size_t)n * 32 + t]);         // self
    int e = beg;
    for (; e + 4 <= end; e += 4) {
        int s0 = g_srcs[e], s1 = g_srcs[e + 1], s2 = g_srcs[e + 2], s3 = g_srcs[e + 3];
        uint4 u0 = hr[(size_t)s0 * 32 + t];
        uint4 u1 = hr[(size_t)s1 * 32 + t];
        uint4 u2 = hr[(size_t)s2 * 32 + t];
        uint4 u3 = hr[(size_t)s3 * 32 + t];
        acc8(a, u0); acc8(a, u1); acc8(a, u2); acc8(a, u3);
    }
    for (; e < end; e++) acc8(a, hr[(size_t)g_srcs[e] * 32 + t]);
    float isn = g_is[n];
    unsigned short hh[8];
#pragma unroll
    for (int k = 0; k < 8; k++) {
        __nv_bfloat16 h = __float2bfloat16(fmaxf(isn * a[k] + bias[8 * t + k], 0.0f));
        hh[k] = *reinterpret_cast<unsigned short*>(&h);
    }
    *(uint4*)(oh + (size_t)n * HID + 8 * t) = *(uint4*)hh;
}
// layer 4: 16 thr/node, 4 halfs each; + bias + log_softmax
__global__ __launch_bounds__(256) void agg40_lsm_kernel(
    const float* __restrict__ b4, float* __restrict__ out) {
    int n = blockIdx.x * 16 + (threadIdx.x >> 4);
    int t = threadIdx.x & 15;                // cols [4t, 4t+4)
    if (n >= NNODES) return;
    const uint2* hr = reinterpret_cast<const uint2*>(g_hs4h);
    int beg = g_rowptr[n], end = g_rowptr[n + 1];
    float a[4] = {0.f, 0.f, 0.f, 0.f};
    acc4(a, hr[(size_t)n * 16 + t]);
    int e = beg;
    for (; e + 4 <= end; e += 4) {
        int s0 = g_srcs[e], s1 = g_srcs[e + 1], s2 = g_srcs[e + 2], s3 = g_srcs[e + 3];
        uint2 u0 = hr[(size_t)s0 * 16 + t];
        uint2 u1 = hr[(size_t)s1 * 16 + t];
        uint2 u2 = hr[(size_t)s2 * 16 + t];
        uint2 u3 = hr[(size_t)s3 * 16 + t];
        acc4(a, u0); acc4(a, u1); acc4(a, u2); acc4(a, u3);
    }
    for (; e < end; e++) acc4(a, hr[(size_t)g_srcs[e] * 16 + t]);
    float sc = g_is[n];
    int col0 = 4 * t;
    float v[4];
#pragma unroll
    for (int k = 0; k < 4; k++)
        v[k] = (col0 + k < NCLS) ? (sc * a[k] + b4[col0 + k]) : -1e30f;
    float m = fmaxf(fmaxf(v[0], v[1]), fmaxf(v[2], v[3]));
#pragma unroll
    for (int off = 8; off; off >>= 1) m = fmaxf(m, __shfl_xor_sync(0xffffffffu, m, off));
    float se = 0.f;
#pragma unroll
    for (int k = 0; k < 4; k++) se += (col0 + k < NCLS) ? __expf(v[k] - m) : 0.f;
#pragma unroll
    for (int off = 8; off; off >>= 1) se += __shfl_xor_sync(0xffffffffu, se, off);
    float lse = m + __logf(se);
    if (t < 10) {
        float4 o;
        o.x = v[0] - lse; o.y = v[1] - lse; o.z = v[2] - lse; o.w = v[3] - lse;
        *(float4*)(out + (size_t)n * NCLS + col0) = o;
    }
}

// ================= single-bf16 HMMA GEMM, cp.async pipelined =================
// C[M,NT] = A[m,:K] @ B[n,:K]^T, fp32 accum, one mma pass.
// MODE 0: Ch[m,n] = D * g_is[m] (fp16); MODE 1: relu(D + bias[n]) -> Cb (bf16).
#define ASTR 72

template <int KT, int BN_T, int MODE>
__global__ __launch_bounds__(256, 2) void mma_gemm_kernel(
    const __nv_bfloat16* __restrict__ A,
    const __nv_bfloat16* __restrict__ B,
    int NT,
    __half* __restrict__ Ch,
    __nv_bfloat16* __restrict__ Cb,
    const float* __restrict__ bias)
{
    extern __shared__ __nv_bfloat16 sm[];
    constexpr int NCH = KT / 64;
    constexpr int BSTR = KT + 8;
    constexpr int ASTG_B = 128 * ASTR * 2;     // 18432 bytes per stage
    constexpr int ABUF_B = 2 * ASTG_B;         // 36864 bytes (2 stages)

    const int tid = threadIdx.x;
    const int lane = tid & 31;
    const int wid = tid >> 5;
    const int wm = wid & 3;
    const int wn = wid >> 2;
    constexpr int WN = BN_T / 2;
    constexpr int NTILES = WN / 8;

    const int row0 = blockIdx.x * 128;
    const int col0 = blockIdx.y * BN_T;

    const uint32_t uS = smem_u32(sm);
    const uint32_t uB = uS + ABUF_B;

    auto loadA = [&](int c) {
        int k0 = c * 64;
        uint32_t ab = uS + (c & 1) * ASTG_B;
#pragma unroll
        for (int it = 0; it < 4; it++) {
            int idx = tid + it * 256;          // 1024 16B units
            int r = idx >> 3, q = idx & 7;
            int gr = row0 + r;
            int sz = (gr < NNODES) ? 16 : 0;
            cp_async16(ab + (uint32_t)(r * ASTR + q * 8) * 2,
                       A + (size_t)gr * KT + k0 + q * 8, sz);
        }
    };

    {
        constexpr int BUNITS = BN_T * KT / 8;
        for (int u = tid; u < BUNITS; u += 256) {
            int n = u / (KT / 8), q = u % (KT / 8);
            cp_async16(uB + (uint32_t)(n * BSTR + q * 8) * 2,
                       B + (size_t)(col0 + n) * KT + q * 8, 16);
        }
        loadA(0);
        CP_COMMIT();
    }

    float acc[2][NTILES][4];
#pragma unroll
    for (int i = 0; i < 2; i++)
#pragma unroll
        for (int j = 0; j < NTILES; j++)
#pragma unroll
            for (int q = 0; q < 4; q++) acc[i][j][q] = 0.0f;

    const int a_r = (lane & 7) + ((lane >> 3) & 1) * 8;
    const int a_k = (lane >> 4) * 8;
    const int b_n = (lane & 7) + ((lane >> 4) & 1) * 8;
    const int b_k = ((lane >> 3) & 1) * 8;

#pragma unroll
    for (int c = 0; c < NCH; c++) {
        if (c + 1 < NCH) {
            loadA(c + 1);
            CP_COMMIT();
            asm volatile("cp.async.wait_group 1;");
        } else {
            asm volatile("cp.async.wait_group 0;");
        }
        __syncthreads();

        uint32_t ab = uS + (c & 1) * ASTG_B;
#pragma unroll
        for (int ks = 0; ks < 4; ks++) {
            uint32_t ah[2][4];
#pragma unroll
            for (int mt = 0; mt < 2; mt++) {
                uint32_t off = (uint32_t)(((wm * 32 + mt * 16 + a_r) * ASTR + ks * 16 + a_k) * 2);
                ldsm_x4(ah[mt][0], ah[mt][1], ah[mt][2], ah[mt][3], ab + off);
            }
            uint32_t bh[NTILES][2];
#pragma unroll
            for (int nb = 0; nb < NTILES / 2; nb++) {
                uint32_t off = (uint32_t)(((wn * WN + nb * 16 + b_n) * BSTR + c * 64 + ks * 16 + b_k) * 2);
                uint32_t r0, r1, r2, r3;
                ldsm_x4(r0, r1, r2, r3, uB + off);
                bh[nb * 2][0] = r0; bh[nb * 2][1] = r1;
                bh[nb * 2 + 1][0] = r2; bh[nb * 2 + 1][1] = r3;
            }
#pragma unroll
            for (int mt = 0; mt < 2; mt++)
#pragma unroll
                for (int nt = 0; nt < NTILES; nt++)
                    mma16816(acc[mt][nt][0], acc[mt][nt][1], acc[mt][nt][2], acc[mt][nt][3],
                             ah[mt][0], ah[mt][1], ah[mt][2], ah[mt][3], bh[nt][0], bh[nt][1]);
        }
        __syncthreads();
    }

    // ---- epilogue ----
    const int rbase = row0 + wm * 32 + (lane >> 2);
    const int cbase = col0 + wn * WN + ((lane & 3) * 2);
#pragma unroll
    for (int mt = 0; mt < 2; mt++) {
#pragma unroll
        for (int half = 0; half < 2; half++) {
            int gr = rbase + mt * 16 + half * 8;
            if (gr < NNODES) {
                if (MODE == 0) {
                    float s = g_is[gr];
#pragma unroll
                    for (int nt = 0; nt < NTILES; nt++) {
                        __half2 p = __floats2half2_rn(acc[mt][nt][half * 2 + 0] * s,
                                                      acc[mt][nt][half * 2 + 1] * s);
                        *(__half2*)(Ch + (size_t)gr * NT + cbase + nt * 8) = p;
                    }
                } else {
#pragma unroll
                    for (int nt = 0; nt < NTILES; nt++) {
                        int c = cbase + nt * 8;
                        float v0 = fmaxf(acc[mt][nt][half * 2 + 0] + bias[c], 0.0f);
                        float v1 = fmaxf(acc[mt][nt][half * 2 + 1] + bias[c + 1], 0.0f);
                        __nv_bfloat162 hp;
                        hp.x = __float2bfloat16(v0);
                        hp.y = __float2bfloat16(v1);
                        *(__nv_bfloat162*)(Cb + (size_t)gr * NT + c) = hp;
                    }
                }
            }
        }
    }
}

// ================= launch =================
extern "C" void kernel_launch(void* const* d_in, const int* in_sizes, int n_in,
                              void* d_out, int out_size)
{
    const float* x  = (const float*)d_in[0];
    const int*   ei = (const int*)  d_in[1];
    const float* W1 = (const float*)d_in[2];
    const float* b1 = (const float*)d_in[3];
    const float* W2 = (const float*)d_in[4];
    const float* b2 = (const float*)d_in[5];
    const float* W3 = (const float*)d_in[6];
    const float* b3 = (const float*)d_in[7];
    const float* W4 = (const float*)d_in[8];
    const float* b4 = (const float*)d_in[9];
    float* out = (float*)d_out;

    const int* src = ei;
    const int* dst = ei + NEDGES;

    __nv_bfloat16 *tptr, *h0, *h1, *wt1, *wt2, *wt3, *wt4;
    __half *hsh, *hs4h;
    int *cntp, *fillp;
    cudaGetSymbolAddress((void**)&tptr, g_t);
    cudaGetSymbolAddress((void**)&h0,  g_h0);
    cudaGetSymbolAddress((void**)&h1,  g_h1);
    cudaGetSymbolAddress((void**)&wt1, g_wt1);
    cudaGetSymbolAddress((void**)&wt2, g_wt2);
    cudaGetSymbolAddress((void**)&wt3, g_wt3);
    cudaGetSymbolAddress((void**)&wt4, g_wt4);
    cudaGetSymbolAddress((void**)&hsh,  g_hsh);
    cudaGetSymbolAddress((void**)&hs4h, g_hs4h);
    cudaGetSymbolAddress((void**)&cntp, g_cnt);
    cudaGetSymbolAddress((void**)&fillp, g_fill);

    // smem: A 2-stage 36864B + B = BN*(KT+8)*2B
    const int SMEM_L1 = 36864 + 128 * (128 + 8) * 2;  // 71680
    const int SMEM_L2 = 36864 + 128 * (256 + 8) * 2;  // 104448
    const int SMEM_L4 = 36864 + 64  * (256 + 8) * 2;  // 70656
    cudaFuncSetAttribute(mma_gemm_kernel<128, 128, 1>, cudaFuncAttributeMaxDynamicSharedMemorySize, SMEM_L1);
    cudaFuncSetAttribute(mma_gemm_kernel<256, 128, 0>, cudaFuncAttributeMaxDynamicSharedMemorySize, SMEM_L2);
    cudaFuncSetAttribute(mma_gemm_kernel<256, 64, 0>,  cudaFuncAttributeMaxDynamicSharedMemorySize, SMEM_L4);

    const int TB = 256;
    int edgeBlocks = (NEDGES + TB - 1) / TB;

    // ---- graph build ----
    cudaMemsetAsync(cntp, 0, NNODES * sizeof(int));
    cudaMemsetAsync(fillp, 0, NNODES * sizeof(int));
    degree_kernel<<<edgeBlocks, TB>>>(dst);
    scan_block_kernel<<<NB_SCAN, 1024>>>();
    scan_tops_kernel<<<1, 64>>>();
    scan_add_kernel<<<NB_SCAN, 1024>>>();
    fill_kernel<<<edgeBlocks, TB>>>(src, dst);

    // ---- weight + x prep ----
    const int WALL = W1E + W2E + W3E + W4E;
    wprep_all_kernel<<<(WALL + TB - 1) / TB, TB>>>(W1, W2, W3, W4);
    xprep_kernel<<<(NNODES * FIN / 4 + TB - 1) / TB, TB>>>((const float4*)x);

    int mBlocks = (NNODES + 127) / 128;          // 391
    dim3 gHID(mBlocks, 2);
    dim3 gC(mBlocks, 1);
    int warpNodeBlocks = (NNODES + 7) / 8;       // 6250
    int a40Blocks = (NNODES + 15) / 16;          // 3125

    // layer 1: aggregate-first (fp16 gather), GEMM fused bias+relu
    agg_x_kernel<<<warpNodeBlocks, TB>>>();
    mma_gemm_kernel<128, 128, 1><<<gHID, 256, SMEM_L1>>>(
        tptr, wt1, HID, nullptr, h0, b1);
    // layer 2
    mma_gemm_kernel<256, 128, 0><<<gHID, 256, SMEM_L2>>>(
        h0, wt2, HID, hsh, nullptr, nullptr);
    agg_mid_kernel<<<warpNodeBlocks, TB>>>(hsh, b2, h1);
    // layer 3
    mma_gemm_kernel<256, 128, 0><<<gHID, 256, SMEM_L2>>>(
        h1, wt3, HID, hsh, nullptr, nullptr);
    agg_mid_kernel<<<warpNodeBlocks, TB>>>(hsh, b3, h0);
    // layer 4 + log_softmax
    mma_gemm_kernel<256, 64, 0><<<gC, 256, SMEM_L4>>>(
        h0, wt4, CPAD, hs4h, nullptr, nullptr);
    agg40_lsm_kernel<<<a40Blocks, TB>>>(b4, out);
}